// round 1
// baseline (speedup 1.0000x reference)
#include <cuda_runtime.h>

#define B_N      262144
#define OFF_ETA  33554432   // B*128
#define OFF_SCAL 34340864   // B*131
#define OFF_DEC  34340866

__device__ int g_cnt[3];    // [0]: eta_v!=eta_b, [1]: eta_t!=eta_b, [2]: eta_v!=eta_t

__device__ __forceinline__ float fsqrt_ap(float x){ float r; asm("sqrt.approx.f32 %0,%1;":"=f"(r):"f"(x)); return r; }
__device__ __forceinline__ float frcp_ap (float x){ float r; asm("rcp.approx.f32 %0,%1;" :"=f"(r):"f"(x)); return r; }

// Abramowitz-Stegun 4.4.46: acos(x) = sqrt(1-x)*poly(x), |err| <= 2e-8 on [0,1]
__device__ __forceinline__ float acos_fast(float x){
    float ax = fabsf(x);
    float p = fmaf(ax, -0.0012624911f, 0.0066700901f);
    p = fmaf(p, ax, -0.0170881256f);
    p = fmaf(p, ax,  0.0308918810f);
    p = fmaf(p, ax, -0.0501743046f);
    p = fmaf(p, ax,  0.0889789874f);
    p = fmaf(p, ax, -0.2145988016f);
    p = fmaf(p, ax,  1.5707963050f);
    float r = fsqrt_ap(1.0f - ax) * p;
    return (x < 0.0f) ? (3.14159274f - r) : r;
}

__global__ void __launch_bounds__(256)
bridge_kernel(const float* __restrict__ vis, const int* __restrict__ txt,
              const float* __restrict__ Wv,  const float* __restrict__ bv,
              const float* __restrict__ Wt,  const float* __restrict__ bt,
              const float* __restrict__ Wd,  const float* __restrict__ bd,
              float* __restrict__ out)
{
    __shared__ float sW[1024];          // [0,384) Wv | [384,512) bv | [512,640) Wt | [640,768) bt | [768,1024) Wd
    __shared__ float sQ[8][3][16];      // per-warp sampled quats (v,t,b) rows 0,8,16,24
    __shared__ int   scnt[3];

    int tid = threadIdx.x;
    for (int i = tid; i < 384; i += 256) sW[i] = Wv[i];
    if (tid < 128){ sW[384+tid] = bv[tid]; sW[512+tid] = Wt[tid]; sW[640+tid] = bt[tid]; }
    sW[768+tid] = Wd[tid];
    if (tid < 3) scnt[tid] = 0;
    __syncthreads();

    int warp = tid >> 5, lane = tid & 31;
    int row  = (blockIdx.x << 3) + warp;

    float vx = vis[row*3+0], vy = vis[row*3+1], vz = vis[row*3+2];
    float tf = (float)txt[row];

    int j = lane << 2;  // quaternion base index into 128-dim atom vector

    // ---- project to SU(2): v modality ----
    float v0 = fmaf(vx, sW[(j+0)*3+0], fmaf(vy, sW[(j+0)*3+1], fmaf(vz, sW[(j+0)*3+2], sW[384+j+0])));
    float v1 = fmaf(vx, sW[(j+1)*3+0], fmaf(vy, sW[(j+1)*3+1], fmaf(vz, sW[(j+1)*3+2], sW[384+j+1])));
    float v2 = fmaf(vx, sW[(j+2)*3+0], fmaf(vy, sW[(j+2)*3+1], fmaf(vz, sW[(j+2)*3+2], sW[384+j+2])));
    float v3 = fmaf(vx, sW[(j+3)*3+0], fmaf(vy, sW[(j+3)*3+1], fmaf(vz, sW[(j+3)*3+2], sW[384+j+3])));
    float inv = frcp_ap(fsqrt_ap(v0*v0 + v1*v1 + v2*v2 + v3*v3) + 1e-8f);
    v0 *= inv; v1 *= inv; v2 *= inv; v3 *= inv;

    // ---- t modality ----
    float t0 = fmaf(tf, sW[512+j+0], sW[640+j+0]);
    float t1 = fmaf(tf, sW[512+j+1], sW[640+j+1]);
    float t2 = fmaf(tf, sW[512+j+2], sW[640+j+2]);
    float t3 = fmaf(tf, sW[512+j+3], sW[640+j+3]);
    inv = frcp_ap(fsqrt_ap(t0*t0 + t1*t1 + t2*t2 + t3*t3) + 1e-8f);
    t0 *= inv; t1 *= inv; t2 *= inv; t3 *= inv;

    // ---- barycenter init: normalized chord mean ----
    float b0 = 0.5f*(v0+t0), b1 = 0.5f*(v1+t1), b2 = 0.5f*(v2+t2), b3 = 0.5f*(v3+t3);
    inv = frcp_ap(fsqrt_ap(b0*b0 + b1*b1 + b2*b2 + b3*b3) + 1e-8f);
    b0 *= inv; b1 *= inv; b2 *= inv; b3 *= inv;

    // ---- Karcher flow, 5 iterations ----
    #pragma unroll
    for (int it = 0; it < 5; ++it){
        float g0, g1, g2, g3;
        {   // v contribution
            float d = v0*b0 + v1*b1 + v2*b2 + v3*b3;
            d = fminf(fmaxf(d, -1.0f + 1e-6f), 1.0f - 1e-6f);
            float th = acos_fast(d);
            float p0 = fmaf(-d, b0, v0), p1 = fmaf(-d, b1, v1);
            float p2 = fmaf(-d, b2, v2), p3 = fmaf(-d, b3, v3);
            float s = th * frcp_ap(fsqrt_ap(p0*p0 + p1*p1 + p2*p2 + p3*p3) + 1e-8f);
            g0 = s*p0; g1 = s*p1; g2 = s*p2; g3 = s*p3;
        }
        {   // t contribution
            float d = t0*b0 + t1*b1 + t2*b2 + t3*b3;
            d = fminf(fmaxf(d, -1.0f + 1e-6f), 1.0f - 1e-6f);
            float th = acos_fast(d);
            float p0 = fmaf(-d, b0, t0), p1 = fmaf(-d, b1, t1);
            float p2 = fmaf(-d, b2, t2), p3 = fmaf(-d, b3, t3);
            float s = th * frcp_ap(fsqrt_ap(p0*p0 + p1*p1 + p2*p2 + p3*p3) + 1e-8f);
            g0 = fmaf(s, p0, g0); g1 = fmaf(s, p1, g1);
            g2 = fmaf(s, p2, g2); g3 = fmaf(s, p3, g3);
        }
        g0 *= 0.5f; g1 *= 0.5f; g2 *= 0.5f; g3 *= 0.5f;
        float tn = fsqrt_ap(g0*g0 + g1*g1 + g2*g2 + g3*g3);
        float ct = __cosf(tn), st = __sinf(tn);
        float k  = st * frcp_ap(tn + 1e-8f);
        b0 = fmaf(ct, b0, k*g0); b1 = fmaf(ct, b1, k*g1);
        b2 = fmaf(ct, b2, k*g2); b3 = fmaf(ct, b3, k*g3);
        float in2 = frcp_ap(fsqrt_ap(b0*b0 + b1*b1 + b2*b2 + b3*b3) + 1e-8f);
        b0 *= in2; b1 *= in2; b2 *= in2; b3 *= in2;
    }

    // ---- barycenter store (coalesced float4) ----
    *reinterpret_cast<float4*>(out + (size_t)row*128 + j) = make_float4(b0, b1, b2, b3);

    // ---- eta: publish sampled quats (indices 0,8,16,24) ----
    if ((lane & 7) == 0){
        int r4 = (lane >> 3) << 2;
        float* q;
        q = &sQ[warp][0][r4]; q[0]=v0; q[1]=v1; q[2]=v2; q[3]=v3;
        q = &sQ[warp][1][r4]; q[0]=t0; q[1]=t1; q[2]=t2; q[3]=t3;
        q = &sQ[warp][2][r4]; q[0]=b0; q[1]=b1; q[2]=b2; q[3]=b3;
    }
    __syncwarp();

    float eta = 0.0f;
    if (lane < 3){
        const float* M = sQ[warp][lane];
        float a00=M[0], a01=M[1], a02=M[2], a03=M[3];
        float a10=M[4], a11=M[5], a12=M[6], a13=M[7];
        float a20=M[8], a21=M[9], a22=M[10],a23=M[11];
        float a30=M[12],a31=M[13],a32=M[14],a33=M[15];
        float s0 = a00*a11 - a01*a10;
        float s1 = a00*a12 - a02*a10;
        float s2 = a00*a13 - a03*a10;
        float s3 = a01*a12 - a02*a11;
        float s4 = a01*a13 - a03*a11;
        float s5 = a02*a13 - a03*a12;
        float c5 = a22*a33 - a23*a32;
        float c4 = a21*a33 - a23*a31;
        float c3 = a21*a32 - a22*a31;
        float c2 = a20*a33 - a23*a30;
        float c1 = a20*a32 - a22*a30;
        float c0 = a20*a31 - a21*a30;
        float det = s0*c5 - s1*c4 + s2*c3 + s3*c2 - s4*c1 + s5*c0;
        eta = (det < 0.0f) ? 1.0f : 0.0f;
        out[OFF_ETA + lane*B_N + row] = eta;
    }
    float ev = __shfl_sync(0xffffffffu, eta, 0);
    float et = __shfl_sync(0xffffffffu, eta, 1);
    float eb = __shfl_sync(0xffffffffu, eta, 2);
    if (lane == 0){
        if (ev != eb) atomicAdd(&scnt[0], 1);
        if (et != eb) atomicAdd(&scnt[1], 1);
        if (ev != et) atomicAdd(&scnt[2], 1);
    }

    // ---- decision = barycenter @ Wd.T + bd ----
    float d0 = b0*sW[768+j] + b1*sW[768+j+1] + b2*sW[768+j+2] + b3*sW[768+j+3];
    float d1 = b0*sW[896+j] + b1*sW[896+j+1] + b2*sW[896+j+2] + b3*sW[896+j+3];
    #pragma unroll
    for (int o = 16; o; o >>= 1){
        d0 += __shfl_down_sync(0xffffffffu, d0, o);
        d1 += __shfl_down_sync(0xffffffffu, d1, o);
    }
    if (lane == 0){
        out[OFF_DEC + row*2 + 0] = d0 + bd[0];
        out[OFF_DEC + row*2 + 1] = d1 + bd[1];
    }

    __syncthreads();
    if (tid < 3 && scnt[tid]) atomicAdd(&g_cnt[tid], scnt[tid]);
}

__global__ void init_kernel(){
    if (threadIdx.x < 3) g_cnt[threadIdx.x] = 0;
}

__global__ void fin_kernel(float* __restrict__ out){
    out[OFF_SCAL + 0] = sqrtf((float)g_cnt[0]) + sqrtf((float)g_cnt[1]);
    out[OFF_SCAL + 1] = (float)g_cnt[2] * (1.0f / 262144.0f);
}

extern "C" void kernel_launch(void* const* d_in, const int* in_sizes, int n_in,
                              void* d_out, int out_size)
{
    const float* vis = (const float*)d_in[0];
    const int*   txt = (const int*)  d_in[1];
    const float* Wv  = (const float*)d_in[2];
    const float* bv  = (const float*)d_in[3];
    const float* Wt  = (const float*)d_in[4];
    const float* bt  = (const float*)d_in[5];
    const float* Wd  = (const float*)d_in[6];
    const float* bd  = (const float*)d_in[7];
    float* out = (float*)d_out;

    init_kernel<<<1, 32>>>();
    bridge_kernel<<<32768, 256>>>(vis, txt, Wv, bv, Wt, bt, Wd, bd, out);
    fin_kernel<<<1, 1>>>(out);
}

// round 3
// speedup vs baseline: 1.7910x; 1.7910x over previous
#include <cuda_runtime.h>

#define B_N      262144
#define OFF_ETA  33554432   // B*128
#define OFF_SCAL 34340864   // B*131
#define OFF_DEC  34340866

__device__ int g_cnt[3];    // [0]: eta_v!=eta_b, [1]: eta_t!=eta_b, [2]: eta_v!=eta_t

__device__ __forceinline__ float frsqrt_ap(float x){ float r; asm("rsqrt.approx.f32 %0,%1;":"=f"(r):"f"(x)); return r; }
// Safe normalization factor: matches reference q/(norm+1e-8) including the exact-zero case
// (zero vector -> finite inv -> 0*inv = 0, no NaN).
__device__ __forceinline__ float inv_norm(float n2){ return frsqrt_ap(fmaxf(n2, 1e-20f)); }

__global__ void __launch_bounds__(256)
bridge_kernel(const float* __restrict__ vis, const int* __restrict__ txt,
              const float* __restrict__ Wv,  const float* __restrict__ bv,
              const float* __restrict__ Wt,  const float* __restrict__ bt,
              const float* __restrict__ Wd,  const float* __restrict__ bd,
              float* __restrict__ out)
{
    __shared__ float sW[1024];          // [0,384) Wv | [384,512) bv | [512,640) Wt | [640,768) bt | [768,1024) Wd
    __shared__ float sQ[8][3][16];      // per-warp sampled quats (v,t,b) rows 0,8,16,24
    __shared__ int   scnt[3];

    int tid = threadIdx.x;
    for (int i = tid; i < 384; i += 256) sW[i] = Wv[i];
    if (tid < 128){ sW[384+tid] = bv[tid]; sW[512+tid] = Wt[tid]; sW[640+tid] = bt[tid]; }
    sW[768+tid] = Wd[tid];
    if (tid < 3) scnt[tid] = 0;
    __syncthreads();

    int warp = tid >> 5, lane = tid & 31;
    int row  = (blockIdx.x << 3) + warp;

    float vx = vis[row*3+0], vy = vis[row*3+1], vz = vis[row*3+2];
    float tf = (float)txt[row];

    int j = lane << 2;  // quaternion base index into 128-dim atom vector

    // ---- project to SU(2): v modality ----
    float v0 = fmaf(vx, sW[(j+0)*3+0], fmaf(vy, sW[(j+0)*3+1], fmaf(vz, sW[(j+0)*3+2], sW[384+j+0])));
    float v1 = fmaf(vx, sW[(j+1)*3+0], fmaf(vy, sW[(j+1)*3+1], fmaf(vz, sW[(j+1)*3+2], sW[384+j+1])));
    float v2 = fmaf(vx, sW[(j+2)*3+0], fmaf(vy, sW[(j+2)*3+1], fmaf(vz, sW[(j+2)*3+2], sW[384+j+2])));
    float v3 = fmaf(vx, sW[(j+3)*3+0], fmaf(vy, sW[(j+3)*3+1], fmaf(vz, sW[(j+3)*3+2], sW[384+j+3])));
    float inv = inv_norm(fmaf(v0,v0, fmaf(v1,v1, fmaf(v2,v2, v3*v3))));
    v0 *= inv; v1 *= inv; v2 *= inv; v3 *= inv;

    // ---- t modality (t_atoms can be EXACTLY zero when txt==0: inv_norm keeps it 0, not NaN) ----
    float t0 = fmaf(tf, sW[512+j+0], sW[640+j+0]);
    float t1 = fmaf(tf, sW[512+j+1], sW[640+j+1]);
    float t2 = fmaf(tf, sW[512+j+2], sW[640+j+2]);
    float t3 = fmaf(tf, sW[512+j+3], sW[640+j+3]);
    inv = inv_norm(fmaf(t0,t0, fmaf(t1,t1, fmaf(t2,t2, t3*t3))));
    t0 *= inv; t1 *= inv; t2 *= inv; t3 *= inv;

    // ---- barycenter: normalized chord mean == Karcher fixed point for 2 points ----
    // (dot(v,b)==dot(t,b), perp_v + perp_t == 0 exactly => the 5-iteration flow is a no-op;
    //  for the t==0 rows the tangent is parallel to b, also a no-op)
    float b0 = v0+t0, b1 = v1+t1, b2 = v2+t2, b3 = v3+t3;
    inv = inv_norm(fmaf(b0,b0, fmaf(b1,b1, fmaf(b2,b2, b3*b3))));
    b0 *= inv; b1 *= inv; b2 *= inv; b3 *= inv;

    // ---- barycenter store (coalesced float4) ----
    *reinterpret_cast<float4*>(out + (size_t)row*128 + j) = make_float4(b0, b1, b2, b3);

    // ---- eta: publish sampled quats (indices 0,8,16,24) ----
    if ((lane & 7) == 0){
        int r4 = (lane >> 3) << 2;
        float* q;
        q = &sQ[warp][0][r4]; q[0]=v0; q[1]=v1; q[2]=v2; q[3]=v3;
        q = &sQ[warp][1][r4]; q[0]=t0; q[1]=t1; q[2]=t2; q[3]=t3;
        q = &sQ[warp][2][r4]; q[0]=b0; q[1]=b1; q[2]=b2; q[3]=b3;
    }
    __syncwarp();

    float eta = 0.0f;
    if (lane < 3){
        const float* M = sQ[warp][lane];
        float a00=M[0], a01=M[1], a02=M[2], a03=M[3];
        float a10=M[4], a11=M[5], a12=M[6], a13=M[7];
        float a20=M[8], a21=M[9], a22=M[10],a23=M[11];
        float a30=M[12],a31=M[13],a32=M[14],a33=M[15];
        float s0 = a00*a11 - a01*a10;
        float s1 = a00*a12 - a02*a10;
        float s2 = a00*a13 - a03*a10;
        float s3 = a01*a12 - a02*a11;
        float s4 = a01*a13 - a03*a11;
        float s5 = a02*a13 - a03*a12;
        float c5 = a22*a33 - a23*a32;
        float c4 = a21*a33 - a23*a31;
        float c3 = a21*a32 - a22*a31;
        float c2 = a20*a33 - a23*a30;
        float c1 = a20*a32 - a22*a30;
        float c0 = a20*a31 - a21*a30;
        float det = s0*c5 - s1*c4 + s2*c3 + s3*c2 - s4*c1 + s5*c0;
        eta = (det < 0.0f) ? 1.0f : 0.0f;
        out[OFF_ETA + lane*B_N + row] = eta;
    }
    float ev = __shfl_sync(0xffffffffu, eta, 0);
    float et = __shfl_sync(0xffffffffu, eta, 1);
    float eb = __shfl_sync(0xffffffffu, eta, 2);
    if (lane == 0){
        if (ev != eb) atomicAdd(&scnt[0], 1);
        if (et != eb) atomicAdd(&scnt[1], 1);
        if (ev != et) atomicAdd(&scnt[2], 1);
    }

    // ---- decision = barycenter @ Wd.T + bd ----
    float d0 = b0*sW[768+j] + b1*sW[768+j+1] + b2*sW[768+j+2] + b3*sW[768+j+3];
    float d1 = b0*sW[896+j] + b1*sW[896+j+1] + b2*sW[896+j+2] + b3*sW[896+j+3];
    #pragma unroll
    for (int o = 16; o; o >>= 1){
        d0 += __shfl_down_sync(0xffffffffu, d0, o);
        d1 += __shfl_down_sync(0xffffffffu, d1, o);
    }
    if (lane == 0){
        out[OFF_DEC + row*2 + 0] = d0 + bd[0];
        out[OFF_DEC + row*2 + 1] = d1 + bd[1];
    }

    __syncthreads();
    if (tid < 3 && scnt[tid]) atomicAdd(&g_cnt[tid], scnt[tid]);
}

__global__ void init_kernel(){
    if (threadIdx.x < 3) g_cnt[threadIdx.x] = 0;
}

__global__ void fin_kernel(float* __restrict__ out){
    out[OFF_SCAL + 0] = sqrtf((float)g_cnt[0]) + sqrtf((float)g_cnt[1]);
    out[OFF_SCAL + 1] = (float)g_cnt[2] * (1.0f / 262144.0f);
}

extern "C" void kernel_launch(void* const* d_in, const int* in_sizes, int n_in,
                              void* d_out, int out_size)
{
    const float* vis = (const float*)d_in[0];
    const int*   txt = (const int*)  d_in[1];
    const float* Wv  = (const float*)d_in[2];
    const float* bv  = (const float*)d_in[3];
    const float* Wt  = (const float*)d_in[4];
    const float* bt  = (const float*)d_in[5];
    const float* Wd  = (const float*)d_in[6];
    const float* bd  = (const float*)d_in[7];
    float* out = (float*)d_out;

    init_kernel<<<1, 32>>>();
    bridge_kernel<<<32768, 256>>>(vis, txt, Wv, bv, Wt, bt, Wd, bd, out);
    fin_kernel<<<1, 1>>>(out);
}

// round 4
// speedup vs baseline: 2.4192x; 1.3508x over previous
#include <cuda_runtime.h>

#define B_N      262144
#define OFF_ETA  33554432   // B*128
#define OFF_SCAL 34340864   // B*131
#define OFF_DEC  34340866

#define NBLK 1184           // 8 blocks/SM target; grid-stride by warp
#define NWARPS (NBLK * 8)

__device__ int g_cnt[3];    // [0]: eta_v!=eta_b, [1]: eta_t!=eta_b, [2]: eta_v!=eta_t

__device__ __forceinline__ float frsqrt_ap(float x){ float r; asm("rsqrt.approx.f32 %0,%1;":"=f"(r):"f"(x)); return r; }
// Matches reference q/(norm+1e-8) incl. exact-zero vectors (finite inv -> 0*inv = 0).
__device__ __forceinline__ float inv_norm(float n2){ return frsqrt_ap(fmaxf(n2, 1e-20f)); }

__global__ void __launch_bounds__(256)
bridge_kernel(const float* __restrict__ vis, const int* __restrict__ txt,
              const float* __restrict__ Wv,  const float* __restrict__ bv,
              const float* __restrict__ Wt,  const float* __restrict__ bt,
              const float* __restrict__ Wd,  const float* __restrict__ bd,
              float* __restrict__ out)
{
    __shared__ float sQ[8][2][3][16];   // [warp][parity][v,t,b][4x4 sampled quats]

    int tid = threadIdx.x, warp = tid >> 5, lane = tid & 31;
    int j = lane << 2;

    // ---- weights in registers, loaded once per persistent warp ----
    float wv[4][3], bvr[4], wtr[4], btr[4], wd0[4], wd1[4];
    #pragma unroll
    for (int k = 0; k < 4; ++k){
        wv[k][0] = __ldg(&Wv[(j+k)*3+0]);
        wv[k][1] = __ldg(&Wv[(j+k)*3+1]);
        wv[k][2] = __ldg(&Wv[(j+k)*3+2]);
        bvr[k]   = __ldg(&bv[j+k]);
        wtr[k]   = __ldg(&Wt[j+k]);
        btr[k]   = __ldg(&bt[j+k]);
        wd0[k]   = __ldg(&Wd[j+k]);
        wd1[k]   = __ldg(&Wd[128+j+k]);
    }
    float bd0 = __ldg(&bd[0]), bd1 = __ldg(&bd[1]);

    int gwarp = blockIdx.x * 8 + warp;
    int c0 = 0, c1 = 0, c2 = 0;
    int parity = 0;

    for (int row = gwarp; row < B_N; row += NWARPS, parity ^= 1){
        float vx = __ldg(&vis[row*3+0]);
        float vy = __ldg(&vis[row*3+1]);
        float vz = __ldg(&vis[row*3+2]);
        float tf = (float)__ldg(&txt[row]);

        // ---- v modality ----
        float v0 = fmaf(vx, wv[0][0], fmaf(vy, wv[0][1], fmaf(vz, wv[0][2], bvr[0])));
        float v1 = fmaf(vx, wv[1][0], fmaf(vy, wv[1][1], fmaf(vz, wv[1][2], bvr[1])));
        float v2 = fmaf(vx, wv[2][0], fmaf(vy, wv[2][1], fmaf(vz, wv[2][2], bvr[2])));
        float v3 = fmaf(vx, wv[3][0], fmaf(vy, wv[3][1], fmaf(vz, wv[3][2], bvr[3])));
        float inv = inv_norm(fmaf(v0,v0, fmaf(v1,v1, fmaf(v2,v2, v3*v3))));
        v0 *= inv; v1 *= inv; v2 *= inv; v3 *= inv;

        // ---- t modality (exactly zero when txt==0: stays 0, no NaN) ----
        float t0 = fmaf(tf, wtr[0], btr[0]);
        float t1 = fmaf(tf, wtr[1], btr[1]);
        float t2 = fmaf(tf, wtr[2], btr[2]);
        float t3 = fmaf(tf, wtr[3], btr[3]);
        inv = inv_norm(fmaf(t0,t0, fmaf(t1,t1, fmaf(t2,t2, t3*t3))));
        t0 *= inv; t1 *= inv; t2 *= inv; t3 *= inv;

        // ---- barycenter: normalized chord mean == Karcher fixed point (2 points) ----
        float b0 = v0+t0, b1 = v1+t1, b2 = v2+t2, b3 = v3+t3;
        inv = inv_norm(fmaf(b0,b0, fmaf(b1,b1, fmaf(b2,b2, b3*b3))));
        b0 *= inv; b1 *= inv; b2 *= inv; b3 *= inv;

        *reinterpret_cast<float4*>(out + (size_t)row*128 + j) = make_float4(b0, b1, b2, b3);

        // ---- eta: publish sampled quats (atom indices 0,8,16,24) ----
        float (*q)[16] = sQ[warp][parity];
        if ((lane & 7) == 0){
            int r4 = (lane >> 3) << 2;
            q[0][r4+0]=v0; q[0][r4+1]=v1; q[0][r4+2]=v2; q[0][r4+3]=v3;
            q[1][r4+0]=t0; q[1][r4+1]=t1; q[1][r4+2]=t2; q[1][r4+3]=t3;
            q[2][r4+0]=b0; q[2][r4+1]=b1; q[2][r4+2]=b2; q[2][r4+3]=b3;
        }
        __syncwarp();

        float eta = 0.0f;
        if (lane < 3){
            const float* M = q[lane];
            float a00=M[0], a01=M[1], a02=M[2], a03=M[3];
            float a10=M[4], a11=M[5], a12=M[6], a13=M[7];
            float a20=M[8], a21=M[9], a22=M[10],a23=M[11];
            float a30=M[12],a31=M[13],a32=M[14],a33=M[15];
            float s0 = a00*a11 - a01*a10;
            float s1 = a00*a12 - a02*a10;
            float s2 = a00*a13 - a03*a10;
            float s3 = a01*a12 - a02*a11;
            float s4 = a01*a13 - a03*a11;
            float s5 = a02*a13 - a03*a12;
            float c5 = a22*a33 - a23*a32;
            float c4 = a21*a33 - a23*a31;
            float c3 = a21*a32 - a22*a31;
            float c2d= a20*a33 - a23*a30;
            float c1d= a20*a32 - a22*a30;
            float c0d= a20*a31 - a21*a30;
            float det = s0*c5 - s1*c4 + s2*c3 + s3*c2d - s4*c1d + s5*c0d;
            eta = (det < 0.0f) ? 1.0f : 0.0f;
            out[OFF_ETA + lane*B_N + row] = eta;
        }
        float ev = __shfl_sync(0xffffffffu, eta, 0);
        float et = __shfl_sync(0xffffffffu, eta, 1);
        float eb = __shfl_sync(0xffffffffu, eta, 2);
        if (lane == 0){
            c0 += (ev != eb);
            c1 += (et != eb);
            c2 += (ev != et);
        }

        // ---- decision = barycenter @ Wd.T + bd ----
        float d0 = fmaf(b0, wd0[0], fmaf(b1, wd0[1], fmaf(b2, wd0[2], b3*wd0[3])));
        float d1 = fmaf(b0, wd1[0], fmaf(b1, wd1[1], fmaf(b2, wd1[2], b3*wd1[3])));
        #pragma unroll
        for (int o = 16; o; o >>= 1){
            d0 += __shfl_down_sync(0xffffffffu, d0, o);
            d1 += __shfl_down_sync(0xffffffffu, d1, o);
        }
        if (lane == 0){
            out[OFF_DEC + row*2 + 0] = d0 + bd0;
            out[OFF_DEC + row*2 + 1] = d1 + bd1;
        }
    }

    if (lane == 0){
        if (c0) atomicAdd(&g_cnt[0], c0);
        if (c1) atomicAdd(&g_cnt[1], c1);
        if (c2) atomicAdd(&g_cnt[2], c2);
    }
}

__global__ void init_kernel(){
    if (threadIdx.x < 3) g_cnt[threadIdx.x] = 0;
}

__global__ void fin_kernel(float* __restrict__ out){
    out[OFF_SCAL + 0] = sqrtf((float)g_cnt[0]) + sqrtf((float)g_cnt[1]);
    out[OFF_SCAL + 1] = (float)g_cnt[2] * (1.0f / 262144.0f);
}

extern "C" void kernel_launch(void* const* d_in, const int* in_sizes, int n_in,
                              void* d_out, int out_size)
{
    const float* vis = (const float*)d_in[0];
    const int*   txt = (const int*)  d_in[1];
    const float* Wv  = (const float*)d_in[2];
    const float* bv  = (const float*)d_in[3];
    const float* Wt  = (const float*)d_in[4];
    const float* bt  = (const float*)d_in[5];
    const float* Wd  = (const float*)d_in[6];
    const float* bd  = (const float*)d_in[7];
    float* out = (float*)d_out;

    init_kernel<<<1, 32>>>();
    bridge_kernel<<<NBLK, 256>>>(vis, txt, Wv, bv, Wt, bt, Wd, bd, out);
    fin_kernel<<<1, 1>>>(out);
}

// round 5
// speedup vs baseline: 4.2411x; 1.7531x over previous
#include <cuda_runtime.h>

#define B_N      262144
#define OFF_ETA  33554432   // B*128
#define OFF_SCAL 34340864   // B*131
#define OFF_DEC  34340866

#define NBLK     444        // persistent blocks (~3/SM at ~80 regs)
#define NWARPS   (NBLK * 8)
#define NTHREADS (NBLK * 256)

__device__ int g_cnt[3];    // [0]: eta_v!=eta_b, [1]: eta_t!=eta_b, [2]: eta_v!=eta_t

__device__ __forceinline__ float frsqrt_ap(float x){ float r; asm("rsqrt.approx.f32 %0,%1;":"=f"(r):"f"(x)); return r; }
// Matches reference q/(norm+1e-8) incl. exact-zero vectors (finite inv -> 0*inv = 0, no NaN).
__device__ __forceinline__ float inv_norm(float n2){ return frsqrt_ap(fmaxf(n2, 1e-20f)); }

// eta of a 4x4 matrix given by rows m[0..3][0..3]: 1.0 if det<0 else 0.0
__device__ __forceinline__ float eta4(const float m[4][4]){
    float s0 = m[0][0]*m[1][1] - m[0][1]*m[1][0];
    float s1 = m[0][0]*m[1][2] - m[0][2]*m[1][0];
    float s2 = m[0][0]*m[1][3] - m[0][3]*m[1][0];
    float s3 = m[0][1]*m[1][2] - m[0][2]*m[1][1];
    float s4 = m[0][1]*m[1][3] - m[0][3]*m[1][1];
    float s5 = m[0][2]*m[1][3] - m[0][3]*m[1][2];
    float c5 = m[2][2]*m[3][3] - m[2][3]*m[3][2];
    float c4 = m[2][1]*m[3][3] - m[2][3]*m[3][1];
    float c3 = m[2][1]*m[3][2] - m[2][2]*m[3][1];
    float c2 = m[2][0]*m[3][3] - m[2][3]*m[3][0];
    float c1 = m[2][0]*m[3][2] - m[2][2]*m[3][0];
    float c0 = m[2][0]*m[3][1] - m[2][1]*m[3][0];
    float det = s0*c5 - s1*c4 + s2*c3 + s3*c2 - s4*c1 + s5*c0;
    return (det < 0.0f) ? 1.0f : 0.0f;
}

__global__ void __launch_bounds__(256)
bridge_kernel(const float* __restrict__ vis, const int* __restrict__ txt,
              const float* __restrict__ Wv,  const float* __restrict__ bv,
              const float* __restrict__ Wt,  const float* __restrict__ bt,
              const float* __restrict__ Wd,  const float* __restrict__ bd,
              float* __restrict__ out)
{
    // Shared weights for phase 2 (eta): sampled quats 0,8,16,24 -> dims q*32+k
    __shared__ float sWv[48], sbv[16], sWt[16], sbt[16];

    int tid = threadIdx.x, warp = tid >> 5, lane = tid & 31;
    int j = lane << 2;

    if (tid < 48){
        int q = tid / 12, r = (tid % 12) / 3, c = tid % 3;
        sWv[tid] = Wv[(q*32 + r)*3 + c];
    } else if (tid < 64){
        int k = tid - 48; sbv[k] = bv[(k>>2)*32 + (k&3)];
    } else if (tid < 80){
        int k = tid - 64; sWt[k] = Wt[(k>>2)*32 + (k&3)];
    } else if (tid < 96){
        int k = tid - 80; sbt[k] = bt[(k>>2)*32 + (k&3)];
    }
    __syncthreads();

    // ---- phase-1 weights in registers (per-lane slice j..j+3) ----
    float wv[4][3], bvr[4], wtr[4], btr[4], wd0[4], wd1[4];
    #pragma unroll
    for (int k = 0; k < 4; ++k){
        wv[k][0] = __ldg(&Wv[(j+k)*3+0]);
        wv[k][1] = __ldg(&Wv[(j+k)*3+1]);
        wv[k][2] = __ldg(&Wv[(j+k)*3+2]);
        bvr[k]   = __ldg(&bv[j+k]);
        wtr[k]   = __ldg(&Wt[j+k]);
        btr[k]   = __ldg(&bt[j+k]);
        wd0[k]   = __ldg(&Wd[j+k]);
        wd1[k]   = __ldg(&Wd[128+j+k]);
    }
    float bd0 = __ldg(&bd[0]), bd1 = __ldg(&bd[1]);

    // ================= phase 1: barycenter + decision (warp per row) =================
    int gwarp = blockIdx.x * 8 + warp;
    for (int row = gwarp; row < B_N; row += NWARPS){
        float vx = __ldg(&vis[row*3+0]);
        float vy = __ldg(&vis[row*3+1]);
        float vz = __ldg(&vis[row*3+2]);
        float tf = (float)__ldg(&txt[row]);

        float v0 = fmaf(vx, wv[0][0], fmaf(vy, wv[0][1], fmaf(vz, wv[0][2], bvr[0])));
        float v1 = fmaf(vx, wv[1][0], fmaf(vy, wv[1][1], fmaf(vz, wv[1][2], bvr[1])));
        float v2 = fmaf(vx, wv[2][0], fmaf(vy, wv[2][1], fmaf(vz, wv[2][2], bvr[2])));
        float v3 = fmaf(vx, wv[3][0], fmaf(vy, wv[3][1], fmaf(vz, wv[3][2], bvr[3])));
        float inv = inv_norm(fmaf(v0,v0, fmaf(v1,v1, fmaf(v2,v2, v3*v3))));
        v0 *= inv; v1 *= inv; v2 *= inv; v3 *= inv;

        float t0 = fmaf(tf, wtr[0], btr[0]);
        float t1 = fmaf(tf, wtr[1], btr[1]);
        float t2 = fmaf(tf, wtr[2], btr[2]);
        float t3 = fmaf(tf, wtr[3], btr[3]);
        inv = inv_norm(fmaf(t0,t0, fmaf(t1,t1, fmaf(t2,t2, t3*t3))));
        t0 *= inv; t1 *= inv; t2 *= inv; t3 *= inv;

        // normalized chord mean == Karcher fixed point for 2 points
        float b0 = v0+t0, b1 = v1+t1, b2 = v2+t2, b3 = v3+t3;
        inv = inv_norm(fmaf(b0,b0, fmaf(b1,b1, fmaf(b2,b2, b3*b3))));
        b0 *= inv; b1 *= inv; b2 *= inv; b3 *= inv;

        // streaming store: barycenter will not be re-read, keep it out of L2's way
        __stcs(reinterpret_cast<float4*>(out + (size_t)row*128 + j), make_float4(b0,b1,b2,b3));

        // decision = barycenter @ Wd.T + bd, folded dual warp reduction
        float d0 = fmaf(b0, wd0[0], fmaf(b1, wd0[1], fmaf(b2, wd0[2], b3*wd0[3])));
        float d1 = fmaf(b0, wd1[0], fmaf(b1, wd1[1], fmaf(b2, wd1[2], b3*wd1[3])));
        d0 += __shfl_xor_sync(0xffffffffu, d0, 16);
        d1 += __shfl_xor_sync(0xffffffffu, d1, 16);
        float z = (lane < 16) ? d0 : d1;     // halves now hold independent partials
        #pragma unroll
        for (int o = 8; o; o >>= 1) z += __shfl_xor_sync(0xffffffffu, z, o);
        float zd1 = __shfl_sync(0xffffffffu, z, 16);
        if (lane == 0)
            *reinterpret_cast<float2*>(out + OFF_DEC + row*2) = make_float2(z + bd0, zd1 + bd1);
    }

    // ================= phase 2: eta + flip counts (thread per row) =================
    int gtid = blockIdx.x * 256 + tid;
    int c0 = 0, c1 = 0, c2 = 0;
    for (int row = gtid; row < B_N; row += NTHREADS){
        float vx = __ldg(&vis[row*3+0]);
        float vy = __ldg(&vis[row*3+1]);
        float vz = __ldg(&vis[row*3+2]);
        float tf = (float)__ldg(&txt[row]);

        float Mv[4][4], Mt[4][4], Mb[4][4];
        #pragma unroll
        for (int q = 0; q < 4; ++q){
            float a0 = fmaf(vx, sWv[q*12+0], fmaf(vy, sWv[q*12+1],  fmaf(vz, sWv[q*12+2],  sbv[q*4+0])));
            float a1 = fmaf(vx, sWv[q*12+3], fmaf(vy, sWv[q*12+4],  fmaf(vz, sWv[q*12+5],  sbv[q*4+1])));
            float a2 = fmaf(vx, sWv[q*12+6], fmaf(vy, sWv[q*12+7],  fmaf(vz, sWv[q*12+8],  sbv[q*4+2])));
            float a3 = fmaf(vx, sWv[q*12+9], fmaf(vy, sWv[q*12+10], fmaf(vz, sWv[q*12+11], sbv[q*4+3])));
            float inv = inv_norm(fmaf(a0,a0, fmaf(a1,a1, fmaf(a2,a2, a3*a3))));
            Mv[q][0]=a0*inv; Mv[q][1]=a1*inv; Mv[q][2]=a2*inv; Mv[q][3]=a3*inv;

            float u0 = fmaf(tf, sWt[q*4+0], sbt[q*4+0]);
            float u1 = fmaf(tf, sWt[q*4+1], sbt[q*4+1]);
            float u2 = fmaf(tf, sWt[q*4+2], sbt[q*4+2]);
            float u3 = fmaf(tf, sWt[q*4+3], sbt[q*4+3]);
            inv = inv_norm(fmaf(u0,u0, fmaf(u1,u1, fmaf(u2,u2, u3*u3))));
            Mt[q][0]=u0*inv; Mt[q][1]=u1*inv; Mt[q][2]=u2*inv; Mt[q][3]=u3*inv;

            float w0 = Mv[q][0]+Mt[q][0], w1 = Mv[q][1]+Mt[q][1];
            float w2 = Mv[q][2]+Mt[q][2], w3 = Mv[q][3]+Mt[q][3];
            inv = inv_norm(fmaf(w0,w0, fmaf(w1,w1, fmaf(w2,w2, w3*w3))));
            Mb[q][0]=w0*inv; Mb[q][1]=w1*inv; Mb[q][2]=w2*inv; Mb[q][3]=w3*inv;
        }
        float ev = eta4(Mv), et = eta4(Mt), eb = eta4(Mb);
        out[OFF_ETA + 0*B_N + row] = ev;
        out[OFF_ETA + 1*B_N + row] = et;
        out[OFF_ETA + 2*B_N + row] = eb;

        unsigned m0 = __ballot_sync(0xffffffffu, ev != eb);
        unsigned m1 = __ballot_sync(0xffffffffu, et != eb);
        unsigned m2 = __ballot_sync(0xffffffffu, ev != et);
        if (lane == 0){ c0 += __popc(m0); c1 += __popc(m1); c2 += __popc(m2); }
    }
    if (lane == 0){
        if (c0) atomicAdd(&g_cnt[0], c0);
        if (c1) atomicAdd(&g_cnt[1], c1);
        if (c2) atomicAdd(&g_cnt[2], c2);
    }
}

__global__ void fin_kernel(float* __restrict__ out){
    out[OFF_SCAL + 0] = sqrtf((float)g_cnt[0]) + sqrtf((float)g_cnt[1]);
    out[OFF_SCAL + 1] = (float)g_cnt[2] * (1.0f / 262144.0f);
    // reset for the next graph replay (module-load zero-init covers the first call)
    g_cnt[0] = 0; g_cnt[1] = 0; g_cnt[2] = 0;
}

extern "C" void kernel_launch(void* const* d_in, const int* in_sizes, int n_in,
                              void* d_out, int out_size)
{
    const float* vis = (const float*)d_in[0];
    const int*   txt = (const int*)  d_in[1];
    const float* Wv  = (const float*)d_in[2];
    const float* bv  = (const float*)d_in[3];
    const float* Wt  = (const float*)d_in[4];
    const float* bt  = (const float*)d_in[5];
    const float* Wd  = (const float*)d_in[6];
    const float* bd  = (const float*)d_in[7];
    float* out = (float*)d_out;

    bridge_kernel<<<NBLK, 256>>>(vis, txt, Wv, bv, Wt, bt, Wd, bd, out);
    fin_kernel<<<1, 1>>>(out);
}

// round 6
// speedup vs baseline: 5.6277x; 1.3270x over previous
#include <cuda_runtime.h>

#define B_N      262144
#define OFF_ETA  33554432   // B*128
#define OFF_SCAL 34340864   // B*131
#define OFF_DEC  34340866

#define NBLK     444        // persistent blocks
#define NWARPS   (NBLK * 8)
#define NTHREADS (NBLK * 256)

__device__ int g_cnt[3];    // [0]: eta_v!=eta_b, [1]: eta_t!=eta_b, [2]: eta_v!=eta_t
__device__ int g_done;

typedef unsigned long long u64;

__device__ __forceinline__ float frsqrt_ap(float x){ float r; asm("rsqrt.approx.f32 %0,%1;":"=f"(r):"f"(x)); return r; }
// Matches reference q/(norm+1e-8) incl. exact-zero vectors (finite inv -> 0*inv = 0, no NaN).
__device__ __forceinline__ float inv_norm(float n2){ return frsqrt_ap(fmaxf(n2, 1e-20f)); }

// ---- packed f32x2 helpers (sm_100+; ptxas never emits FFMA2 from C++) ----
__device__ __forceinline__ u64 pk(float lo, float hi){ u64 r; asm("mov.b64 %0,{%1,%2};":"=l"(r):"f"(lo),"f"(hi)); return r; }
__device__ __forceinline__ void upk(float& lo, float& hi, u64 v){ asm("mov.b64 {%0,%1},%2;":"=f"(lo),"=f"(hi):"l"(v)); }
__device__ __forceinline__ u64 fma2(u64 a, u64 b, u64 c){ u64 r; asm("fma.rn.f32x2 %0,%1,%2,%3;":"=l"(r):"l"(a),"l"(b),"l"(c)); return r; }
__device__ __forceinline__ u64 mul2(u64 a, u64 b){ u64 r; asm("mul.rn.f32x2 %0,%1,%2;":"=l"(r):"l"(a),"l"(b)); return r; }
__device__ __forceinline__ u64 add2(u64 a, u64 b){ u64 r; asm("add.rn.f32x2 %0,%1,%2;":"=l"(r):"l"(a),"l"(b)); return r; }
__device__ __forceinline__ float hsum2(u64 a, u64 b){ // dot-tail: sum of 4 packed lanes
    u64 s = add2(a, b); float lo, hi; upk(lo, hi, s); return lo + hi;
}

// eta of a 4x4 matrix: 1.0 if det<0 else 0.0
__device__ __forceinline__ float eta4(const float m[4][4]){
    float s0 = m[0][0]*m[1][1] - m[0][1]*m[1][0];
    float s1 = m[0][0]*m[1][2] - m[0][2]*m[1][0];
    float s2 = m[0][0]*m[1][3] - m[0][3]*m[1][0];
    float s3 = m[0][1]*m[1][2] - m[0][2]*m[1][1];
    float s4 = m[0][1]*m[1][3] - m[0][3]*m[1][1];
    float s5 = m[0][2]*m[1][3] - m[0][3]*m[1][2];
    float c5 = m[2][2]*m[3][3] - m[2][3]*m[3][2];
    float c4 = m[2][1]*m[3][3] - m[2][3]*m[3][1];
    float c3 = m[2][1]*m[3][2] - m[2][2]*m[3][1];
    float c2 = m[2][0]*m[3][3] - m[2][3]*m[3][0];
    float c1 = m[2][0]*m[3][2] - m[2][2]*m[3][0];
    float c0 = m[2][0]*m[3][1] - m[2][1]*m[3][0];
    float det = s0*c5 - s1*c4 + s2*c3 + s3*c2 - s4*c1 + s5*c0;
    return (det < 0.0f) ? 1.0f : 0.0f;
}

__global__ void __launch_bounds__(256)
bridge_kernel(const float* __restrict__ vis, const int* __restrict__ txt,
              const float* __restrict__ Wv,  const float* __restrict__ bv,
              const float* __restrict__ Wt,  const float* __restrict__ bt,
              const float* __restrict__ Wd,  const float* __restrict__ bd,
              float* __restrict__ out)
{
    // Shared weights for phase 2 (eta): sampled quats 0,8,16,24 -> dims q*32+k
    __shared__ float sWv[48], sbv[16], sWt[16], sbt[16];

    int tid = threadIdx.x, warp = tid >> 5, lane = tid & 31;
    int j = lane << 2;

    if (tid < 48){
        int q = tid / 12, r = (tid % 12) / 3, c = tid % 3;
        sWv[tid] = Wv[(q*32 + r)*3 + c];
    } else if (tid < 64){
        int k = tid - 48; sbv[k] = bv[(k>>2)*32 + (k&3)];
    } else if (tid < 80){
        int k = tid - 64; sWt[k] = Wt[(k>>2)*32 + (k&3)];
    } else if (tid < 96){
        int k = tid - 80; sbt[k] = bt[(k>>2)*32 + (k&3)];
    }
    __syncthreads();

    // ---- phase-1 weights, packed into f32x2 registers (lane slice j..j+3) ----
    u64 wx01 = pk(__ldg(&Wv[(j+0)*3+0]), __ldg(&Wv[(j+1)*3+0]));
    u64 wx23 = pk(__ldg(&Wv[(j+2)*3+0]), __ldg(&Wv[(j+3)*3+0]));
    u64 wy01 = pk(__ldg(&Wv[(j+0)*3+1]), __ldg(&Wv[(j+1)*3+1]));
    u64 wy23 = pk(__ldg(&Wv[(j+2)*3+1]), __ldg(&Wv[(j+3)*3+1]));
    u64 wz01 = pk(__ldg(&Wv[(j+0)*3+2]), __ldg(&Wv[(j+1)*3+2]));
    u64 wz23 = pk(__ldg(&Wv[(j+2)*3+2]), __ldg(&Wv[(j+3)*3+2]));
    u64 pbv01 = pk(__ldg(&bv[j+0]), __ldg(&bv[j+1]));
    u64 pbv23 = pk(__ldg(&bv[j+2]), __ldg(&bv[j+3]));
    u64 pwt01 = pk(__ldg(&Wt[j+0]), __ldg(&Wt[j+1]));
    u64 pwt23 = pk(__ldg(&Wt[j+2]), __ldg(&Wt[j+3]));
    u64 pbt01 = pk(__ldg(&bt[j+0]), __ldg(&bt[j+1]));
    u64 pbt23 = pk(__ldg(&bt[j+2]), __ldg(&bt[j+3]));
    u64 pwd0a = pk(__ldg(&Wd[j+0]), __ldg(&Wd[j+1]));
    u64 pwd0b = pk(__ldg(&Wd[j+2]), __ldg(&Wd[j+3]));
    u64 pwd1a = pk(__ldg(&Wd[128+j+0]), __ldg(&Wd[128+j+1]));
    u64 pwd1b = pk(__ldg(&Wd[128+j+2]), __ldg(&Wd[128+j+3]));
    float bd0 = __ldg(&bd[0]), bd1 = __ldg(&bd[1]);

    // ================= phase 1: barycenter + decision (warp per row) =================
    int gwarp = blockIdx.x * 8 + warp;
    for (int row = gwarp; row < B_N; row += NWARPS){
        float vx = __ldg(&vis[row*3+0]);
        float vy = __ldg(&vis[row*3+1]);
        float vz = __ldg(&vis[row*3+2]);
        float tf = (float)__ldg(&txt[row]);
        u64 vxx = pk(vx,vx), vyy = pk(vy,vy), vzz = pk(vz,vz), tff = pk(tf,tf);

        // v = normalize(Wv @ x + bv), two packed halves
        u64 v01 = fma2(vxx, wx01, fma2(vyy, wy01, fma2(vzz, wz01, pbv01)));
        u64 v23 = fma2(vxx, wx23, fma2(vyy, wy23, fma2(vzz, wz23, pbv23)));
        float inv = inv_norm(hsum2(mul2(v01,v01), mul2(v23,v23)));
        u64 pinv = pk(inv, inv);
        v01 = mul2(v01, pinv); v23 = mul2(v23, pinv);

        // t = normalize(tf*Wt + bt)  (exact zero when txt==0 stays zero)
        u64 t01 = fma2(tff, pwt01, pbt01);
        u64 t23 = fma2(tff, pwt23, pbt23);
        inv = inv_norm(hsum2(mul2(t01,t01), mul2(t23,t23)));
        pinv = pk(inv, inv);
        t01 = mul2(t01, pinv); t23 = mul2(t23, pinv);

        // barycenter: normalized chord mean == Karcher fixed point for 2 points
        u64 b01 = add2(v01, t01), b23 = add2(v23, t23);
        inv = inv_norm(hsum2(mul2(b01,b01), mul2(b23,b23)));
        pinv = pk(inv, inv);
        b01 = mul2(b01, pinv); b23 = mul2(b23, pinv);

        float b0, b1, b2, b3; upk(b0, b1, b01); upk(b2, b3, b23);
        // streaming store: barycenter never re-read
        __stcs(reinterpret_cast<float4*>(out + (size_t)row*128 + j), make_float4(b0,b1,b2,b3));

        // decision = barycenter @ Wd.T + bd, folded dual warp reduction
        float d0 = hsum2(mul2(b01, pwd0a), mul2(b23, pwd0b));
        float d1 = hsum2(mul2(b01, pwd1a), mul2(b23, pwd1b));
        d0 += __shfl_xor_sync(0xffffffffu, d0, 16);
        d1 += __shfl_xor_sync(0xffffffffu, d1, 16);
        float z = (lane < 16) ? d0 : d1;     // halves hold independent partials
        #pragma unroll
        for (int o = 8; o; o >>= 1) z += __shfl_xor_sync(0xffffffffu, z, o);
        float zd1 = __shfl_sync(0xffffffffu, z, 16);
        if (lane == 0)
            *reinterpret_cast<float2*>(out + OFF_DEC + row*2) = make_float2(z + bd0, zd1 + bd1);
    }

    // ================= phase 2: eta + flip counts (thread per row) =================
    int gtid = blockIdx.x * 256 + tid;
    int c0 = 0, c1 = 0, c2 = 0;
    for (int row = gtid; row < B_N; row += NTHREADS){
        float vx = __ldg(&vis[row*3+0]);
        float vy = __ldg(&vis[row*3+1]);
        float vz = __ldg(&vis[row*3+2]);
        float tf = (float)__ldg(&txt[row]);

        float Mv[4][4], Mt[4][4], Mb[4][4];
        #pragma unroll
        for (int q = 0; q < 4; ++q){
            float a0 = fmaf(vx, sWv[q*12+0], fmaf(vy, sWv[q*12+1],  fmaf(vz, sWv[q*12+2],  sbv[q*4+0])));
            float a1 = fmaf(vx, sWv[q*12+3], fmaf(vy, sWv[q*12+4],  fmaf(vz, sWv[q*12+5],  sbv[q*4+1])));
            float a2 = fmaf(vx, sWv[q*12+6], fmaf(vy, sWv[q*12+7],  fmaf(vz, sWv[q*12+8],  sbv[q*4+2])));
            float a3 = fmaf(vx, sWv[q*12+9], fmaf(vy, sWv[q*12+10], fmaf(vz, sWv[q*12+11], sbv[q*4+3])));
            float inv = inv_norm(fmaf(a0,a0, fmaf(a1,a1, fmaf(a2,a2, a3*a3))));
            Mv[q][0]=a0*inv; Mv[q][1]=a1*inv; Mv[q][2]=a2*inv; Mv[q][3]=a3*inv;

            float u0 = fmaf(tf, sWt[q*4+0], sbt[q*4+0]);
            float u1 = fmaf(tf, sWt[q*4+1], sbt[q*4+1]);
            float u2 = fmaf(tf, sWt[q*4+2], sbt[q*4+2]);
            float u3 = fmaf(tf, sWt[q*4+3], sbt[q*4+3]);
            inv = inv_norm(fmaf(u0,u0, fmaf(u1,u1, fmaf(u2,u2, u3*u3))));
            Mt[q][0]=u0*inv; Mt[q][1]=u1*inv; Mt[q][2]=u2*inv; Mt[q][3]=u3*inv;

            float w0 = Mv[q][0]+Mt[q][0], w1 = Mv[q][1]+Mt[q][1];
            float w2 = Mv[q][2]+Mt[q][2], w3 = Mv[q][3]+Mt[q][3];
            inv = inv_norm(fmaf(w0,w0, fmaf(w1,w1, fmaf(w2,w2, w3*w3))));
            Mb[q][0]=w0*inv; Mb[q][1]=w1*inv; Mb[q][2]=w2*inv; Mb[q][3]=w3*inv;
        }
        float ev = eta4(Mv), et = eta4(Mt), eb = eta4(Mb);
        out[OFF_ETA + 0*B_N + row] = ev;
        out[OFF_ETA + 1*B_N + row] = et;
        out[OFF_ETA + 2*B_N + row] = eb;

        unsigned m0 = __ballot_sync(0xffffffffu, ev != eb);
        unsigned m1 = __ballot_sync(0xffffffffu, et != eb);
        unsigned m2 = __ballot_sync(0xffffffffu, ev != et);
        if (lane == 0){ c0 += __popc(m0); c1 += __popc(m1); c2 += __popc(m2); }
    }
    if (lane == 0){
        if (c0) atomicAdd(&g_cnt[0], c0);
        if (c1) atomicAdd(&g_cnt[1], c1);
        if (c2) atomicAdd(&g_cnt[2], c2);
    }

    // ---- last-block-done: finalize scalars in-kernel (replaces fin_kernel launch) ----
    __syncthreads();
    if (tid == 0){
        __threadfence();
        int prev = atomicAdd(&g_done, 1);
        if (prev == NBLK - 1){
            int n0 = atomicAdd(&g_cnt[0], 0);
            int n1 = atomicAdd(&g_cnt[1], 0);
            int n2 = atomicAdd(&g_cnt[2], 0);
            out[OFF_SCAL + 0] = sqrtf((float)n0) + sqrtf((float)n1);
            out[OFF_SCAL + 1] = (float)n2 * (1.0f / 262144.0f);
            g_cnt[0] = 0; g_cnt[1] = 0; g_cnt[2] = 0;   // reset for next graph replay
            g_done = 0;
        }
    }
}

extern "C" void kernel_launch(void* const* d_in, const int* in_sizes, int n_in,
                              void* d_out, int out_size)
{
    const float* vis = (const float*)d_in[0];
    const int*   txt = (const int*)  d_in[1];
    const float* Wv  = (const float*)d_in[2];
    const float* bv  = (const float*)d_in[3];
    const float* Wt  = (const float*)d_in[4];
    const float* bt  = (const float*)d_in[5];
    const float* Wd  = (const float*)d_in[6];
    const float* bd  = (const float*)d_in[7];
    float* out = (float*)d_out;

    bridge_kernel<<<NBLK, 256>>>(vis, txt, Wv, bv, Wt, bt, Wd, bd, out);
}

// round 7
// speedup vs baseline: 5.8514x; 1.0397x over previous
#include <cuda_runtime.h>

#define B_N      262144
#define OFF_ETA  33554432   // B*128
#define OFF_SCAL 34340864   // B*131
#define OFF_DEC  34340866

#define NBLK     592        // 4 blocks/SM at 64 regs -> 32 warps/SM
#define NWARPS   (NBLK * 8)
#define NTHREADS (NBLK * 256)

__device__ int g_cnt[3];    // [0]: eta_v!=eta_b, [1]: eta_t!=eta_b, [2]: eta_v!=eta_t
__device__ int g_done;

typedef unsigned long long u64;

__device__ __forceinline__ float frsqrt_ap(float x){ float r; asm("rsqrt.approx.f32 %0,%1;":"=f"(r):"f"(x)); return r; }
// Matches reference q/(norm+1e-8) incl. exact-zero vectors (finite inv -> 0*inv = 0, no NaN).
__device__ __forceinline__ float inv_norm(float n2){ return frsqrt_ap(fmaxf(n2, 1e-20f)); }

// ---- packed f32x2 helpers (sm_100+; ptxas never emits FFMA2 from C++) ----
__device__ __forceinline__ u64 pk(float lo, float hi){ u64 r; asm("mov.b64 %0,{%1,%2};":"=l"(r):"f"(lo),"f"(hi)); return r; }
__device__ __forceinline__ void upk(float& lo, float& hi, u64 v){ asm("mov.b64 {%0,%1},%2;":"=f"(lo),"=f"(hi):"l"(v)); }
__device__ __forceinline__ u64 fma2(u64 a, u64 b, u64 c){ u64 r; asm("fma.rn.f32x2 %0,%1,%2,%3;":"=l"(r):"l"(a),"l"(b),"l"(c)); return r; }
__device__ __forceinline__ u64 mul2(u64 a, u64 b){ u64 r; asm("mul.rn.f32x2 %0,%1,%2;":"=l"(r):"l"(a),"l"(b)); return r; }
__device__ __forceinline__ u64 add2(u64 a, u64 b){ u64 r; asm("add.rn.f32x2 %0,%1,%2;":"=l"(r):"l"(a),"l"(b)); return r; }
__device__ __forceinline__ float hsum2(u64 a, u64 b){ // dot-tail: sum of 4 packed lanes
    u64 s = add2(a, b); float lo, hi; upk(lo, hi, s); return lo + hi;
}

// eta of a 4x4 matrix: 1.0 if det<0 else 0.0
__device__ __forceinline__ float eta4(const float m[4][4]){
    float s0 = m[0][0]*m[1][1] - m[0][1]*m[1][0];
    float s1 = m[0][0]*m[1][2] - m[0][2]*m[1][0];
    float s2 = m[0][0]*m[1][3] - m[0][3]*m[1][0];
    float s3 = m[0][1]*m[1][2] - m[0][2]*m[1][1];
    float s4 = m[0][1]*m[1][3] - m[0][3]*m[1][1];
    float s5 = m[0][2]*m[1][3] - m[0][3]*m[1][2];
    float c5 = m[2][2]*m[3][3] - m[2][3]*m[3][2];
    float c4 = m[2][1]*m[3][3] - m[2][3]*m[3][1];
    float c3 = m[2][1]*m[3][2] - m[2][2]*m[3][1];
    float c2 = m[2][0]*m[3][3] - m[2][3]*m[3][0];
    float c1 = m[2][0]*m[3][2] - m[2][2]*m[3][0];
    float c0 = m[2][0]*m[3][1] - m[2][1]*m[3][0];
    float det = s0*c5 - s1*c4 + s2*c3 + s3*c2 - s4*c1 + s5*c0;
    return (det < 0.0f) ? 1.0f : 0.0f;
}

__global__ void __launch_bounds__(256, 4)
bridge_kernel(const float* __restrict__ vis, const int* __restrict__ txt,
              const float* __restrict__ Wv,  const float* __restrict__ bv,
              const float* __restrict__ Wt,  const float* __restrict__ bt,
              const float* __restrict__ Wd,  const float* __restrict__ bd,
              float* __restrict__ out)
{
    // Shared weights for phase 2 (eta): sampled quats 0,8,16,24 -> dims q*32+k
    __shared__ float sWv[48], sbv[16], sWt[16], sbt[16];

    int tid = threadIdx.x, warp = tid >> 5, lane = tid & 31;
    int j = lane << 2;

    if (tid < 48){
        int q = tid / 12, r = (tid % 12) / 3, c = tid % 3;
        sWv[tid] = Wv[(q*32 + r)*3 + c];
    } else if (tid < 64){
        int k = tid - 48; sbv[k] = bv[(k>>2)*32 + (k&3)];
    } else if (tid < 80){
        int k = tid - 64; sWt[k] = Wt[(k>>2)*32 + (k&3)];
    } else if (tid < 96){
        int k = tid - 80; sbt[k] = bt[(k>>2)*32 + (k&3)];
    }
    __syncthreads();

    // ---- phase-1 weights, packed into f32x2 registers (lane slice j..j+3) ----
    u64 wx01 = pk(__ldg(&Wv[(j+0)*3+0]), __ldg(&Wv[(j+1)*3+0]));
    u64 wx23 = pk(__ldg(&Wv[(j+2)*3+0]), __ldg(&Wv[(j+3)*3+0]));
    u64 wy01 = pk(__ldg(&Wv[(j+0)*3+1]), __ldg(&Wv[(j+1)*3+1]));
    u64 wy23 = pk(__ldg(&Wv[(j+2)*3+1]), __ldg(&Wv[(j+3)*3+1]));
    u64 wz01 = pk(__ldg(&Wv[(j+0)*3+2]), __ldg(&Wv[(j+1)*3+2]));
    u64 wz23 = pk(__ldg(&Wv[(j+2)*3+2]), __ldg(&Wv[(j+3)*3+2]));
    u64 pbv01 = pk(__ldg(&bv[j+0]), __ldg(&bv[j+1]));
    u64 pbv23 = pk(__ldg(&bv[j+2]), __ldg(&bv[j+3]));
    u64 pwt01 = pk(__ldg(&Wt[j+0]), __ldg(&Wt[j+1]));
    u64 pwt23 = pk(__ldg(&Wt[j+2]), __ldg(&Wt[j+3]));
    u64 pbt01 = pk(__ldg(&bt[j+0]), __ldg(&bt[j+1]));
    u64 pbt23 = pk(__ldg(&bt[j+2]), __ldg(&bt[j+3]));
    u64 pwd0a = pk(__ldg(&Wd[j+0]), __ldg(&Wd[j+1]));
    u64 pwd0b = pk(__ldg(&Wd[j+2]), __ldg(&Wd[j+3]));
    u64 pwd1a = pk(__ldg(&Wd[128+j+0]), __ldg(&Wd[128+j+1]));
    u64 pwd1b = pk(__ldg(&Wd[128+j+2]), __ldg(&Wd[128+j+3]));
    float bd0 = __ldg(&bd[0]), bd1 = __ldg(&bd[1]);

    // ================= phase 1: barycenter + decision (warp per row) =================
    int gwarp = blockIdx.x * 8 + warp;
    // prefetch row 0 inputs
    float vx = 0.f, vy = 0.f, vz = 0.f, tf = 0.f;
    if (gwarp < B_N){
        vx = __ldg(&vis[gwarp*3+0]); vy = __ldg(&vis[gwarp*3+1]); vz = __ldg(&vis[gwarp*3+2]);
        tf = (float)__ldg(&txt[gwarp]);
    }
    for (int row = gwarp; row < B_N; row += NWARPS){
        // prefetch next iteration's inputs (clamped: safe, no divergence)
        int nrow = row + NWARPS; nrow = (nrow < B_N) ? nrow : row;
        float nvx = __ldg(&vis[nrow*3+0]);
        float nvy = __ldg(&vis[nrow*3+1]);
        float nvz = __ldg(&vis[nrow*3+2]);
        float ntf = (float)__ldg(&txt[nrow]);

        u64 vxx = pk(vx,vx), vyy = pk(vy,vy), vzz = pk(vz,vz), tff = pk(tf,tf);

        // v = normalize(Wv @ x + bv), two packed halves
        u64 v01 = fma2(vxx, wx01, fma2(vyy, wy01, fma2(vzz, wz01, pbv01)));
        u64 v23 = fma2(vxx, wx23, fma2(vyy, wy23, fma2(vzz, wz23, pbv23)));
        float inv = inv_norm(hsum2(mul2(v01,v01), mul2(v23,v23)));
        u64 pinv = pk(inv, inv);
        v01 = mul2(v01, pinv); v23 = mul2(v23, pinv);

        // t = normalize(tf*Wt + bt)  (exact zero when txt==0 stays zero)
        u64 t01 = fma2(tff, pwt01, pbt01);
        u64 t23 = fma2(tff, pwt23, pbt23);
        inv = inv_norm(hsum2(mul2(t01,t01), mul2(t23,t23)));
        pinv = pk(inv, inv);
        t01 = mul2(t01, pinv); t23 = mul2(t23, pinv);

        // barycenter: normalized chord mean == Karcher fixed point for 2 points
        u64 b01 = add2(v01, t01), b23 = add2(v23, t23);
        inv = inv_norm(hsum2(mul2(b01,b01), mul2(b23,b23)));
        pinv = pk(inv, inv);
        b01 = mul2(b01, pinv); b23 = mul2(b23, pinv);

        float b0, b1, b2, b3; upk(b0, b1, b01); upk(b2, b3, b23);
        // streaming store: barycenter never re-read
        __stcs(reinterpret_cast<float4*>(out + (size_t)row*128 + j), make_float4(b0,b1,b2,b3));

        // decision = barycenter @ Wd.T + bd, folded dual warp reduction
        float d0 = hsum2(mul2(b01, pwd0a), mul2(b23, pwd0b));
        float d1 = hsum2(mul2(b01, pwd1a), mul2(b23, pwd1b));
        d0 += __shfl_xor_sync(0xffffffffu, d0, 16);
        d1 += __shfl_xor_sync(0xffffffffu, d1, 16);
        float z = (lane < 16) ? d0 : d1;     // halves hold independent partials
        #pragma unroll
        for (int o = 8; o; o >>= 1) z += __shfl_xor_sync(0xffffffffu, z, o);
        float zd1 = __shfl_sync(0xffffffffu, z, 16);
        if (lane == 0)
            *reinterpret_cast<float2*>(out + OFF_DEC + row*2) = make_float2(z + bd0, zd1 + bd1);

        vx = nvx; vy = nvy; vz = nvz; tf = ntf;
    }

    // ================= phase 2: eta + flip counts (thread per row) =================
    int gtid = blockIdx.x * 256 + tid;
    int c0 = 0, c1 = 0, c2 = 0;
    for (int row = gtid; row < B_N; row += NTHREADS){
        float px = __ldg(&vis[row*3+0]);
        float py = __ldg(&vis[row*3+1]);
        float pz = __ldg(&vis[row*3+2]);
        float pt = (float)__ldg(&txt[row]);

        float Mv[4][4], Mt[4][4], Mb[4][4];
        #pragma unroll
        for (int q = 0; q < 4; ++q){
            float a0 = fmaf(px, sWv[q*12+0], fmaf(py, sWv[q*12+1],  fmaf(pz, sWv[q*12+2],  sbv[q*4+0])));
            float a1 = fmaf(px, sWv[q*12+3], fmaf(py, sWv[q*12+4],  fmaf(pz, sWv[q*12+5],  sbv[q*4+1])));
            float a2 = fmaf(px, sWv[q*12+6], fmaf(py, sWv[q*12+7],  fmaf(pz, sWv[q*12+8],  sbv[q*4+2])));
            float a3 = fmaf(px, sWv[q*12+9], fmaf(py, sWv[q*12+10], fmaf(pz, sWv[q*12+11], sbv[q*4+3])));
            float inv = inv_norm(fmaf(a0,a0, fmaf(a1,a1, fmaf(a2,a2, a3*a3))));
            Mv[q][0]=a0*inv; Mv[q][1]=a1*inv; Mv[q][2]=a2*inv; Mv[q][3]=a3*inv;

            float u0 = fmaf(pt, sWt[q*4+0], sbt[q*4+0]);
            float u1 = fmaf(pt, sWt[q*4+1], sbt[q*4+1]);
            float u2 = fmaf(pt, sWt[q*4+2], sbt[q*4+2]);
            float u3 = fmaf(pt, sWt[q*4+3], sbt[q*4+3]);
            inv = inv_norm(fmaf(u0,u0, fmaf(u1,u1, fmaf(u2,u2, u3*u3))));
            Mt[q][0]=u0*inv; Mt[q][1]=u1*inv; Mt[q][2]=u2*inv; Mt[q][3]=u3*inv;

            float w0 = Mv[q][0]+Mt[q][0], w1 = Mv[q][1]+Mt[q][1];
            float w2 = Mv[q][2]+Mt[q][2], w3 = Mv[q][3]+Mt[q][3];
            inv = inv_norm(fmaf(w0,w0, fmaf(w1,w1, fmaf(w2,w2, w3*w3))));
            Mb[q][0]=w0*inv; Mb[q][1]=w1*inv; Mb[q][2]=w2*inv; Mb[q][3]=w3*inv;
        }
        float ev = eta4(Mv), et = eta4(Mt), eb = eta4(Mb);
        out[OFF_ETA + 0*B_N + row] = ev;
        out[OFF_ETA + 1*B_N + row] = et;
        out[OFF_ETA + 2*B_N + row] = eb;

        unsigned m0 = __ballot_sync(0xffffffffu, ev != eb);
        unsigned m1 = __ballot_sync(0xffffffffu, et != eb);
        unsigned m2 = __ballot_sync(0xffffffffu, ev != et);
        if (lane == 0){ c0 += __popc(m0); c1 += __popc(m1); c2 += __popc(m2); }
    }
    if (lane == 0){
        if (c0) atomicAdd(&g_cnt[0], c0);
        if (c1) atomicAdd(&g_cnt[1], c1);
        if (c2) atomicAdd(&g_cnt[2], c2);
    }

    // ---- last-block-done: finalize scalars in-kernel ----
    __syncthreads();
    if (tid == 0){
        __threadfence();
        int prev = atomicAdd(&g_done, 1);
        if (prev == NBLK - 1){
            int n0 = atomicAdd(&g_cnt[0], 0);
            int n1 = atomicAdd(&g_cnt[1], 0);
            int n2 = atomicAdd(&g_cnt[2], 0);
            out[OFF_SCAL + 0] = sqrtf((float)n0) + sqrtf((float)n1);
            out[OFF_SCAL + 1] = (float)n2 * (1.0f / 262144.0f);
            g_cnt[0] = 0; g_cnt[1] = 0; g_cnt[2] = 0;   // reset for next graph replay
            g_done = 0;
        }
    }
}

extern "C" void kernel_launch(void* const* d_in, const int* in_sizes, int n_in,
                              void* d_out, int out_size)
{
    const float* vis = (const float*)d_in[0];
    const int*   txt = (const int*)  d_in[1];
    const float* Wv  = (const float*)d_in[2];
    const float* bv  = (const float*)d_in[3];
    const float* Wt  = (const float*)d_in[4];
    const float* bt  = (const float*)d_in[5];
    const float* Wd  = (const float*)d_in[6];
    const float* bd  = (const float*)d_in[7];
    float* out = (float*)d_out;

    bridge_kernel<<<NBLK, 256>>>(vis, txt, Wv, bv, Wt, bt, Wd, bd, out);
}

// round 8
// speedup vs baseline: 6.0380x; 1.0319x over previous
#include <cuda_runtime.h>

#define B_N      262144
#define OFF_ETA  33554432   // B*128
#define OFF_SCAL 34340864   // B*131
#define OFF_DEC  34340866

#define NBLK     444        // 3 blocks/SM (84-reg cap), persistent
#define NWARPS   (NBLK * 8)
#define NTHREADS (NBLK * 256)

__device__ int g_cnt[3];    // [0]: eta_v!=eta_b, [1]: eta_t!=eta_b, [2]: eta_v!=eta_t
__device__ int g_done;

typedef unsigned long long u64;

__device__ __forceinline__ float frsqrt_ap(float x){ float r; asm("rsqrt.approx.f32 %0,%1;":"=f"(r):"f"(x)); return r; }
// Matches reference q/(norm+1e-8) incl. exact-zero vectors (finite inv -> 0*inv = 0, no NaN).
__device__ __forceinline__ float inv_norm(float n2){ return frsqrt_ap(fmaxf(n2, 1e-20f)); }

// ---- packed f32x2 helpers (sm_100+; ptxas never emits FFMA2 from C++) ----
__device__ __forceinline__ u64 pk(float lo, float hi){ u64 r; asm("mov.b64 %0,{%1,%2};":"=l"(r):"f"(lo),"f"(hi)); return r; }
__device__ __forceinline__ void upk(float& lo, float& hi, u64 v){ asm("mov.b64 {%0,%1},%2;":"=f"(lo),"=f"(hi):"l"(v)); }
__device__ __forceinline__ u64 fma2(u64 a, u64 b, u64 c){ u64 r; asm("fma.rn.f32x2 %0,%1,%2,%3;":"=l"(r):"l"(a),"l"(b),"l"(c)); return r; }
__device__ __forceinline__ u64 mul2(u64 a, u64 b){ u64 r; asm("mul.rn.f32x2 %0,%1,%2;":"=l"(r):"l"(a),"l"(b)); return r; }
__device__ __forceinline__ u64 add2(u64 a, u64 b){ u64 r; asm("add.rn.f32x2 %0,%1,%2;":"=l"(r):"l"(a),"l"(b)); return r; }
__device__ __forceinline__ float hsum2(u64 a, u64 b){ // sum of 4 packed lanes
    u64 s = add2(a, b); float lo, hi; upk(lo, hi, s); return lo + hi;
}

// eta of a 4x4 matrix: 1.0 if det<0 else 0.0
__device__ __forceinline__ float eta4(const float m[4][4]){
    float s0 = m[0][0]*m[1][1] - m[0][1]*m[1][0];
    float s1 = m[0][0]*m[1][2] - m[0][2]*m[1][0];
    float s2 = m[0][0]*m[1][3] - m[0][3]*m[1][0];
    float s3 = m[0][1]*m[1][2] - m[0][2]*m[1][1];
    float s4 = m[0][1]*m[1][3] - m[0][3]*m[1][1];
    float s5 = m[0][2]*m[1][3] - m[0][3]*m[1][2];
    float c5 = m[2][2]*m[3][3] - m[2][3]*m[3][2];
    float c4 = m[2][1]*m[3][3] - m[2][3]*m[3][1];
    float c3 = m[2][1]*m[3][2] - m[2][2]*m[3][1];
    float c2 = m[2][0]*m[3][3] - m[2][3]*m[3][0];
    float c1 = m[2][0]*m[3][2] - m[2][2]*m[3][0];
    float c0 = m[2][0]*m[3][1] - m[2][1]*m[3][0];
    float det = s0*c5 - s1*c4 + s2*c3 + s3*c2 - s4*c1 + s5*c0;
    return (det < 0.0f) ? 1.0f : 0.0f;
}

struct RowIn { float vx, vy, vz, tf; };

__global__ void __launch_bounds__(256, 3)
bridge_kernel(const float* __restrict__ vis, const int* __restrict__ txt,
              const float* __restrict__ Wv,  const float* __restrict__ bv,
              const float* __restrict__ Wt,  const float* __restrict__ bt,
              const float* __restrict__ Wd,  const float* __restrict__ bd,
              float* __restrict__ out)
{
    // Shared weights for phase 2 (eta): sampled quats 0,8,16,24 -> dims q*32+k
    __shared__ float sWv[48], sbv[16], sWt[16], sbt[16];

    int tid = threadIdx.x, warp = tid >> 5, lane = tid & 31;
    int j = lane << 2;

    if (tid < 48){
        int q = tid / 12, r = (tid % 12) / 3, c = tid % 3;
        sWv[tid] = Wv[(q*32 + r)*3 + c];
    } else if (tid < 64){
        int k = tid - 48; sbv[k] = bv[(k>>2)*32 + (k&3)];
    } else if (tid < 80){
        int k = tid - 64; sWt[k] = Wt[(k>>2)*32 + (k&3)];
    } else if (tid < 96){
        int k = tid - 80; sbt[k] = bt[(k>>2)*32 + (k&3)];
    }
    __syncthreads();

    // ---- phase-1 weights, packed into f32x2 registers (lane slice j..j+3) ----
    u64 wx01 = pk(__ldg(&Wv[(j+0)*3+0]), __ldg(&Wv[(j+1)*3+0]));
    u64 wx23 = pk(__ldg(&Wv[(j+2)*3+0]), __ldg(&Wv[(j+3)*3+0]));
    u64 wy01 = pk(__ldg(&Wv[(j+0)*3+1]), __ldg(&Wv[(j+1)*3+1]));
    u64 wy23 = pk(__ldg(&Wv[(j+2)*3+1]), __ldg(&Wv[(j+3)*3+1]));
    u64 wz01 = pk(__ldg(&Wv[(j+0)*3+2]), __ldg(&Wv[(j+1)*3+2]));
    u64 wz23 = pk(__ldg(&Wv[(j+2)*3+2]), __ldg(&Wv[(j+3)*3+2]));
    u64 pbv01 = pk(__ldg(&bv[j+0]), __ldg(&bv[j+1]));
    u64 pbv23 = pk(__ldg(&bv[j+2]), __ldg(&bv[j+3]));
    u64 pwt01 = pk(__ldg(&Wt[j+0]), __ldg(&Wt[j+1]));
    u64 pwt23 = pk(__ldg(&Wt[j+2]), __ldg(&Wt[j+3]));
    u64 pbt01 = pk(__ldg(&bt[j+0]), __ldg(&bt[j+1]));
    u64 pbt23 = pk(__ldg(&bt[j+2]), __ldg(&bt[j+3]));
    u64 pwd0a = pk(__ldg(&Wd[j+0]), __ldg(&Wd[j+1]));
    u64 pwd0b = pk(__ldg(&Wd[j+2]), __ldg(&Wd[j+3]));
    u64 pwd1a = pk(__ldg(&Wd[128+j+0]), __ldg(&Wd[128+j+1]));
    u64 pwd1b = pk(__ldg(&Wd[128+j+2]), __ldg(&Wd[128+j+3]));
    float bd0 = __ldg(&bd[0]), bd1 = __ldg(&bd[1]);

    // ============ phase 1: barycenter + decision, 2 rows/iteration (ILP) ============
    int gwarp = blockIdx.x * 8 + warp;

    #define LOADIN(dst, r_) do { int rr = (r_); rr = (rr < B_N) ? rr : 0;            \
        dst.vx = __ldg(&vis[rr*3+0]); dst.vy = __ldg(&vis[rr*3+1]);                  \
        dst.vz = __ldg(&vis[rr*3+2]); dst.tf = (float)__ldg(&txt[rr]); } while(0)

    RowIn inA, inB;
    LOADIN(inA, gwarp);
    LOADIN(inB, gwarp + NWARPS);

    for (int row = gwarp; row < B_N; row += 2*NWARPS){
        int rowB = row + NWARPS;
        bool okB = rowB < B_N;

        RowIn nA, nB;                       // prefetch next pair (clamped)
        LOADIN(nA, row + 2*NWARPS);
        LOADIN(nB, rowB + 2*NWARPS);

        // ---- row A ----
        u64 axx = pk(inA.vx,inA.vx), ayy = pk(inA.vy,inA.vy), azz = pk(inA.vz,inA.vz), atf = pk(inA.tf,inA.tf);
        u64 Av01 = fma2(axx, wx01, fma2(ayy, wy01, fma2(azz, wz01, pbv01)));
        u64 Av23 = fma2(axx, wx23, fma2(ayy, wy23, fma2(azz, wz23, pbv23)));
        u64 At01 = fma2(atf, pwt01, pbt01);
        u64 At23 = fma2(atf, pwt23, pbt23);
        // ---- row B (independent chain, interleaves with A) ----
        u64 bxx = pk(inB.vx,inB.vx), byy = pk(inB.vy,inB.vy), bzz = pk(inB.vz,inB.vz), btf = pk(inB.tf,inB.tf);
        u64 Bv01 = fma2(bxx, wx01, fma2(byy, wy01, fma2(bzz, wz01, pbv01)));
        u64 Bv23 = fma2(bxx, wx23, fma2(byy, wy23, fma2(bzz, wz23, pbv23)));
        u64 Bt01 = fma2(btf, pwt01, pbt01);
        u64 Bt23 = fma2(btf, pwt23, pbt23);

        float invA = inv_norm(hsum2(mul2(Av01,Av01), mul2(Av23,Av23)));
        float invB = inv_norm(hsum2(mul2(Bv01,Bv01), mul2(Bv23,Bv23)));
        u64 p = pk(invA, invA); Av01 = mul2(Av01, p); Av23 = mul2(Av23, p);
        p = pk(invB, invB);     Bv01 = mul2(Bv01, p); Bv23 = mul2(Bv23, p);

        invA = inv_norm(hsum2(mul2(At01,At01), mul2(At23,At23)));
        invB = inv_norm(hsum2(mul2(Bt01,Bt01), mul2(Bt23,Bt23)));
        p = pk(invA, invA); At01 = mul2(At01, p); At23 = mul2(At23, p);
        p = pk(invB, invB); Bt01 = mul2(Bt01, p); Bt23 = mul2(Bt23, p);

        // barycenter: normalized chord mean == Karcher fixed point for 2 points
        u64 Ab01 = add2(Av01, At01), Ab23 = add2(Av23, At23);
        u64 Bb01 = add2(Bv01, Bt01), Bb23 = add2(Bv23, Bt23);
        invA = inv_norm(hsum2(mul2(Ab01,Ab01), mul2(Ab23,Ab23)));
        invB = inv_norm(hsum2(mul2(Bb01,Bb01), mul2(Bb23,Bb23)));
        p = pk(invA, invA); Ab01 = mul2(Ab01, p); Ab23 = mul2(Ab23, p);
        p = pk(invB, invB); Bb01 = mul2(Bb01, p); Bb23 = mul2(Bb23, p);

        float a0,a1,a2,a3; upk(a0,a1,Ab01); upk(a2,a3,Ab23);
        __stcs(reinterpret_cast<float4*>(out + (size_t)row*128 + j), make_float4(a0,a1,a2,a3));
        if (okB){
            float q0,q1,q2,q3; upk(q0,q1,Bb01); upk(q2,q3,Bb23);
            __stcs(reinterpret_cast<float4*>(out + (size_t)rowB*128 + j), make_float4(q0,q1,q2,q3));
        }

        // decisions: two folded dual reductions, chains interleave
        float dA0 = hsum2(mul2(Ab01, pwd0a), mul2(Ab23, pwd0b));
        float dA1 = hsum2(mul2(Ab01, pwd1a), mul2(Ab23, pwd1b));
        float dB0 = hsum2(mul2(Bb01, pwd0a), mul2(Bb23, pwd0b));
        float dB1 = hsum2(mul2(Bb01, pwd1a), mul2(Bb23, pwd1b));
        dA0 += __shfl_xor_sync(0xffffffffu, dA0, 16);
        dA1 += __shfl_xor_sync(0xffffffffu, dA1, 16);
        dB0 += __shfl_xor_sync(0xffffffffu, dB0, 16);
        dB1 += __shfl_xor_sync(0xffffffffu, dB1, 16);
        float zA = (lane < 16) ? dA0 : dA1;
        float zB = (lane < 16) ? dB0 : dB1;
        #pragma unroll
        for (int o = 8; o; o >>= 1){
            zA += __shfl_xor_sync(0xffffffffu, zA, o);
            zB += __shfl_xor_sync(0xffffffffu, zB, o);
        }
        float zA1 = __shfl_sync(0xffffffffu, zA, 16);
        float zB1 = __shfl_sync(0xffffffffu, zB, 16);
        if (lane == 0){
            *reinterpret_cast<float2*>(out + OFF_DEC + row*2) = make_float2(zA + bd0, zA1 + bd1);
            if (okB)
                *reinterpret_cast<float2*>(out + OFF_DEC + rowB*2) = make_float2(zB + bd0, zB1 + bd1);
        }

        inA = nA; inB = nB;
    }
    #undef LOADIN

    // ================= phase 2: eta + flip counts (thread per row) =================
    int gtid = blockIdx.x * 256 + tid;
    int c0 = 0, c1 = 0, c2 = 0;
    for (int row = gtid; row < B_N; row += NTHREADS){
        float px = __ldg(&vis[row*3+0]);
        float py = __ldg(&vis[row*3+1]);
        float pz = __ldg(&vis[row*3+2]);
        float pt = (float)__ldg(&txt[row]);

        float Mv[4][4], Mt[4][4], Mb[4][4];
        #pragma unroll
        for (int q = 0; q < 4; ++q){
            float a0 = fmaf(px, sWv[q*12+0], fmaf(py, sWv[q*12+1],  fmaf(pz, sWv[q*12+2],  sbv[q*4+0])));
            float a1 = fmaf(px, sWv[q*12+3], fmaf(py, sWv[q*12+4],  fmaf(pz, sWv[q*12+5],  sbv[q*4+1])));
            float a2 = fmaf(px, sWv[q*12+6], fmaf(py, sWv[q*12+7],  fmaf(pz, sWv[q*12+8],  sbv[q*4+2])));
            float a3 = fmaf(px, sWv[q*12+9], fmaf(py, sWv[q*12+10], fmaf(pz, sWv[q*12+11], sbv[q*4+3])));
            float inv = inv_norm(fmaf(a0,a0, fmaf(a1,a1, fmaf(a2,a2, a3*a3))));
            Mv[q][0]=a0*inv; Mv[q][1]=a1*inv; Mv[q][2]=a2*inv; Mv[q][3]=a3*inv;

            float u0 = fmaf(pt, sWt[q*4+0], sbt[q*4+0]);
            float u1 = fmaf(pt, sWt[q*4+1], sbt[q*4+1]);
            float u2 = fmaf(pt, sWt[q*4+2], sbt[q*4+2]);
            float u3 = fmaf(pt, sWt[q*4+3], sbt[q*4+3]);
            inv = inv_norm(fmaf(u0,u0, fmaf(u1,u1, fmaf(u2,u2, u3*u3))));
            Mt[q][0]=u0*inv; Mt[q][1]=u1*inv; Mt[q][2]=u2*inv; Mt[q][3]=u3*inv;

            float w0 = Mv[q][0]+Mt[q][0], w1 = Mv[q][1]+Mt[q][1];
            float w2 = Mv[q][2]+Mt[q][2], w3 = Mv[q][3]+Mt[q][3];
            inv = inv_norm(fmaf(w0,w0, fmaf(w1,w1, fmaf(w2,w2, w3*w3))));
            Mb[q][0]=w0*inv; Mb[q][1]=w1*inv; Mb[q][2]=w2*inv; Mb[q][3]=w3*inv;
        }
        float ev = eta4(Mv), et = eta4(Mt), eb = eta4(Mb);
        out[OFF_ETA + 0*B_N + row] = ev;
        out[OFF_ETA + 1*B_N + row] = et;
        out[OFF_ETA + 2*B_N + row] = eb;

        unsigned m0 = __ballot_sync(0xffffffffu, ev != eb);
        unsigned m1 = __ballot_sync(0xffffffffu, et != eb);
        unsigned m2 = __ballot_sync(0xffffffffu, ev != et);
        if (lane == 0){ c0 += __popc(m0); c1 += __popc(m1); c2 += __popc(m2); }
    }
    if (lane == 0){
        if (c0) atomicAdd(&g_cnt[0], c0);
        if (c1) atomicAdd(&g_cnt[1], c1);
        if (c2) atomicAdd(&g_cnt[2], c2);
    }

    // ---- last-block-done: finalize scalars in-kernel ----
    __syncthreads();
    if (tid == 0){
        __threadfence();
        int prev = atomicAdd(&g_done, 1);
        if (prev == NBLK - 1){
            int n0 = atomicAdd(&g_cnt[0], 0);
            int n1 = atomicAdd(&g_cnt[1], 0);
            int n2 = atomicAdd(&g_cnt[2], 0);
            out[OFF_SCAL + 0] = sqrtf((float)n0) + sqrtf((float)n1);
            out[OFF_SCAL + 1] = (float)n2 * (1.0f / 262144.0f);
            g_cnt[0] = 0; g_cnt[1] = 0; g_cnt[2] = 0;   // reset for next graph replay
            g_done = 0;
        }
    }
}

extern "C" void kernel_launch(void* const* d_in, const int* in_sizes, int n_in,
                              void* d_out, int out_size)
{
    const float* vis = (const float*)d_in[0];
    const int*   txt = (const int*)  d_in[1];
    const float* Wv  = (const float*)d_in[2];
    const float* bv  = (const float*)d_in[3];
    const float* Wt  = (const float*)d_in[4];
    const float* bt  = (const float*)d_in[5];
    const float* Wd  = (const float*)d_in[6];
    const float* bd  = (const float*)d_in[7];
    float* out = (float*)d_out;

    bridge_kernel<<<NBLK, 256>>>(vis, txt, Wv, bv, Wt, bt, Wd, bd, out);
}

// round 10
// speedup vs baseline: 6.4441x; 1.0673x over previous
#include <cuda_runtime.h>

#define B_N      262144
#define OFF_ETA  33554432   // B*128
#define OFF_SCAL 34340864   // B*131
#define OFF_DEC  34340866

#define NBLK     444        // 3 blocks/SM (84-reg cap), persistent
#define NWARPS   (NBLK * 8)
#define NTHREADS (NBLK * 256)

__device__ int g_cnt[3];    // [0]: eta_v!=eta_b, [1]: eta_t!=eta_b, [2]: eta_v!=eta_t
__device__ int g_done;

typedef unsigned long long u64;

__device__ __forceinline__ float frsqrt_ap(float x){ float r; asm("rsqrt.approx.f32 %0,%1;":"=f"(r):"f"(x)); return r; }
// Matches reference q/(norm+1e-8) incl. exact-zero vectors (finite inv -> 0*inv = 0, no NaN).
__device__ __forceinline__ float inv_norm(float n2){ return frsqrt_ap(fmaxf(n2, 1e-20f)); }

// sm_103: only INTEGER warp redux exists (f32 variant is not supported).
__device__ __forceinline__ int redux_add_s32(int v){
    int r; asm("redux.sync.add.s32 %0, %1, 0xffffffff;" : "=r"(r) : "r"(v)); return r;
}
// Fixed-point scale for decision partials: |partial| < 8 guaranteed (unit quat x Wd~0.1),
// 8*2^23*32 = 2^31 boundary; actual partials ~0.6 -> huge headroom, quant err ~2e-6 abs.
#define FXS  8388608.0f      // 2^23
#define IFXS 1.1920928955078125e-7f  // 2^-23

// ---- packed f32x2 helpers (sm_100+; ptxas never emits FFMA2 from C++) ----
__device__ __forceinline__ u64 pk(float lo, float hi){ u64 r; asm("mov.b64 %0,{%1,%2};":"=l"(r):"f"(lo),"f"(hi)); return r; }
__device__ __forceinline__ void upk(float& lo, float& hi, u64 v){ asm("mov.b64 {%0,%1},%2;":"=f"(lo),"=f"(hi):"l"(v)); }
__device__ __forceinline__ u64 fma2(u64 a, u64 b, u64 c){ u64 r; asm("fma.rn.f32x2 %0,%1,%2,%3;":"=l"(r):"l"(a),"l"(b),"l"(c)); return r; }
__device__ __forceinline__ u64 mul2(u64 a, u64 b){ u64 r; asm("mul.rn.f32x2 %0,%1,%2;":"=l"(r):"l"(a),"l"(b)); return r; }
__device__ __forceinline__ u64 add2(u64 a, u64 b){ u64 r; asm("add.rn.f32x2 %0,%1,%2;":"=l"(r):"l"(a),"l"(b)); return r; }
__device__ __forceinline__ float hsum2(u64 a, u64 b){ // sum of 4 packed lanes
    u64 s = add2(a, b); float lo, hi; upk(lo, hi, s); return lo + hi;
}

// eta of a 4x4 matrix: 1.0 if det<0 else 0.0
__device__ __forceinline__ float eta4(const float m[4][4]){
    float s0 = m[0][0]*m[1][1] - m[0][1]*m[1][0];
    float s1 = m[0][0]*m[1][2] - m[0][2]*m[1][0];
    float s2 = m[0][0]*m[1][3] - m[0][3]*m[1][0];
    float s3 = m[0][1]*m[1][2] - m[0][2]*m[1][1];
    float s4 = m[0][1]*m[1][3] - m[0][3]*m[1][1];
    float s5 = m[0][2]*m[1][3] - m[0][3]*m[1][2];
    float c5 = m[2][2]*m[3][3] - m[2][3]*m[3][2];
    float c4 = m[2][1]*m[3][3] - m[2][3]*m[3][1];
    float c3 = m[2][1]*m[3][2] - m[2][2]*m[3][1];
    float c2 = m[2][0]*m[3][3] - m[2][3]*m[3][0];
    float c1 = m[2][0]*m[3][2] - m[2][2]*m[3][0];
    float c0 = m[2][0]*m[3][1] - m[2][1]*m[3][0];
    float det = s0*c5 - s1*c4 + s2*c3 + s3*c2 - s4*c1 + s5*c0;
    return (det < 0.0f) ? 1.0f : 0.0f;
}

struct RowIn { float vx, vy, vz, tf; };

__global__ void __launch_bounds__(256, 3)
bridge_kernel(const float* __restrict__ vis, const int* __restrict__ txt,
              const float* __restrict__ Wv,  const float* __restrict__ bv,
              const float* __restrict__ Wt,  const float* __restrict__ bt,
              const float* __restrict__ Wd,  const float* __restrict__ bd,
              float* __restrict__ out)
{
    // Shared weights for phase 2 (eta): sampled quats 0,8,16,24 -> dims q*32+k
    __shared__ float sWv[48], sbv[16], sWt[16], sbt[16];

    int tid = threadIdx.x, warp = tid >> 5, lane = tid & 31;
    int j = lane << 2;

    if (tid < 48){
        int q = tid / 12, r = (tid % 12) / 3, c = tid % 3;
        sWv[tid] = Wv[(q*32 + r)*3 + c];
    } else if (tid < 64){
        int k = tid - 48; sbv[k] = bv[(k>>2)*32 + (k&3)];
    } else if (tid < 80){
        int k = tid - 64; sWt[k] = Wt[(k>>2)*32 + (k&3)];
    } else if (tid < 96){
        int k = tid - 80; sbt[k] = bt[(k>>2)*32 + (k&3)];
    }
    __syncthreads();

    // ---- phase-1 weights, packed into f32x2 registers (lane slice j..j+3) ----
    u64 wx01 = pk(__ldg(&Wv[(j+0)*3+0]), __ldg(&Wv[(j+1)*3+0]));
    u64 wx23 = pk(__ldg(&Wv[(j+2)*3+0]), __ldg(&Wv[(j+3)*3+0]));
    u64 wy01 = pk(__ldg(&Wv[(j+0)*3+1]), __ldg(&Wv[(j+1)*3+1]));
    u64 wy23 = pk(__ldg(&Wv[(j+2)*3+1]), __ldg(&Wv[(j+3)*3+1]));
    u64 wz01 = pk(__ldg(&Wv[(j+0)*3+2]), __ldg(&Wv[(j+1)*3+2]));
    u64 wz23 = pk(__ldg(&Wv[(j+2)*3+2]), __ldg(&Wv[(j+3)*3+2]));
    u64 pbv01 = pk(__ldg(&bv[j+0]), __ldg(&bv[j+1]));
    u64 pbv23 = pk(__ldg(&bv[j+2]), __ldg(&bv[j+3]));
    u64 pwt01 = pk(__ldg(&Wt[j+0]), __ldg(&Wt[j+1]));
    u64 pwt23 = pk(__ldg(&Wt[j+2]), __ldg(&Wt[j+3]));
    u64 pbt01 = pk(__ldg(&bt[j+0]), __ldg(&bt[j+1]));
    u64 pbt23 = pk(__ldg(&bt[j+2]), __ldg(&bt[j+3]));
    u64 pwd0a = pk(__ldg(&Wd[j+0]), __ldg(&Wd[j+1]));
    u64 pwd0b = pk(__ldg(&Wd[j+2]), __ldg(&Wd[j+3]));
    u64 pwd1a = pk(__ldg(&Wd[128+j+0]), __ldg(&Wd[128+j+1]));
    u64 pwd1b = pk(__ldg(&Wd[128+j+2]), __ldg(&Wd[128+j+3]));
    float bd0 = __ldg(&bd[0]), bd1 = __ldg(&bd[1]);

    // ============ phase 1: barycenter + decision, 2 rows/iteration (ILP) ============
    int gwarp = blockIdx.x * 8 + warp;

    #define LOADIN(dst, r_) do { int rr = (r_); rr = (rr < B_N) ? rr : 0;            \
        dst.vx = __ldg(&vis[rr*3+0]); dst.vy = __ldg(&vis[rr*3+1]);                  \
        dst.vz = __ldg(&vis[rr*3+2]); dst.tf = (float)__ldg(&txt[rr]); } while(0)

    RowIn inA, inB;
    LOADIN(inA, gwarp);
    LOADIN(inB, gwarp + NWARPS);

    for (int row = gwarp; row < B_N; row += 2*NWARPS){
        int rowB = row + NWARPS;
        bool okB = rowB < B_N;

        RowIn nA, nB;                       // prefetch next pair (clamped)
        LOADIN(nA, row + 2*NWARPS);
        LOADIN(nB, rowB + 2*NWARPS);

        // ---- row A ----
        u64 axx = pk(inA.vx,inA.vx), ayy = pk(inA.vy,inA.vy), azz = pk(inA.vz,inA.vz), atf = pk(inA.tf,inA.tf);
        u64 Av01 = fma2(axx, wx01, fma2(ayy, wy01, fma2(azz, wz01, pbv01)));
        u64 Av23 = fma2(axx, wx23, fma2(ayy, wy23, fma2(azz, wz23, pbv23)));
        u64 At01 = fma2(atf, pwt01, pbt01);
        u64 At23 = fma2(atf, pwt23, pbt23);
        // ---- row B (independent chain, interleaves with A) ----
        u64 bxx = pk(inB.vx,inB.vx), byy = pk(inB.vy,inB.vy), bzz = pk(inB.vz,inB.vz), btf = pk(inB.tf,inB.tf);
        u64 Bv01 = fma2(bxx, wx01, fma2(byy, wy01, fma2(bzz, wz01, pbv01)));
        u64 Bv23 = fma2(bxx, wx23, fma2(byy, wy23, fma2(bzz, wz23, pbv23)));
        u64 Bt01 = fma2(btf, pwt01, pbt01);
        u64 Bt23 = fma2(btf, pwt23, pbt23);

        float invA = inv_norm(hsum2(mul2(Av01,Av01), mul2(Av23,Av23)));
        float invB = inv_norm(hsum2(mul2(Bv01,Bv01), mul2(Bv23,Bv23)));
        u64 p = pk(invA, invA); Av01 = mul2(Av01, p); Av23 = mul2(Av23, p);
        p = pk(invB, invB);     Bv01 = mul2(Bv01, p); Bv23 = mul2(Bv23, p);

        invA = inv_norm(hsum2(mul2(At01,At01), mul2(At23,At23)));
        invB = inv_norm(hsum2(mul2(Bt01,Bt01), mul2(Bt23,Bt23)));
        p = pk(invA, invA); At01 = mul2(At01, p); At23 = mul2(At23, p);
        p = pk(invB, invB); Bt01 = mul2(Bt01, p); Bt23 = mul2(Bt23, p);

        // barycenter: normalized chord mean == Karcher fixed point for 2 points
        u64 Ab01 = add2(Av01, At01), Ab23 = add2(Av23, At23);
        u64 Bb01 = add2(Bv01, Bt01), Bb23 = add2(Bv23, Bt23);
        invA = inv_norm(hsum2(mul2(Ab01,Ab01), mul2(Ab23,Ab23)));
        invB = inv_norm(hsum2(mul2(Bb01,Bb01), mul2(Bb23,Bb23)));
        p = pk(invA, invA); Ab01 = mul2(Ab01, p); Ab23 = mul2(Ab23, p);
        p = pk(invB, invB); Bb01 = mul2(Bb01, p); Bb23 = mul2(Bb23, p);

        float a0,a1,a2,a3; upk(a0,a1,Ab01); upk(a2,a3,Ab23);
        __stcs(reinterpret_cast<float4*>(out + (size_t)row*128 + j), make_float4(a0,a1,a2,a3));
        if (okB){
            float q0,q1,q2,q3; upk(q0,q1,Bb01); upk(q2,q3,Bb23);
            __stcs(reinterpret_cast<float4*>(out + (size_t)rowB*128 + j), make_float4(q0,q1,q2,q3));
        }

        // decisions: per-lane partial dots -> fixed-point -> hardware warp redux (s32)
        int iA0 = __float2int_rn(hsum2(mul2(Ab01, pwd0a), mul2(Ab23, pwd0b)) * FXS);
        int iA1 = __float2int_rn(hsum2(mul2(Ab01, pwd1a), mul2(Ab23, pwd1b)) * FXS);
        int iB0 = __float2int_rn(hsum2(mul2(Bb01, pwd0a), mul2(Bb23, pwd0b)) * FXS);
        int iB1 = __float2int_rn(hsum2(mul2(Bb01, pwd1a), mul2(Bb23, pwd1b)) * FXS);
        int sA0 = redux_add_s32(iA0);
        int sA1 = redux_add_s32(iA1);
        int sB0 = redux_add_s32(iB0);
        int sB1 = redux_add_s32(iB1);
        if (lane == 0){
            *reinterpret_cast<float2*>(out + OFF_DEC + row*2) =
                make_float2(fmaf((float)sA0, IFXS, bd0), fmaf((float)sA1, IFXS, bd1));
            if (okB)
                *reinterpret_cast<float2*>(out + OFF_DEC + rowB*2) =
                    make_float2(fmaf((float)sB0, IFXS, bd0), fmaf((float)sB1, IFXS, bd1));
        }

        inA = nA; inB = nB;
    }
    #undef LOADIN

    // ================= phase 2: eta + flip counts (thread per row) =================
    int gtid = blockIdx.x * 256 + tid;
    int c0 = 0, c1 = 0, c2 = 0;
    for (int row = gtid; row < B_N; row += NTHREADS){
        float px = __ldg(&vis[row*3+0]);
        float py = __ldg(&vis[row*3+1]);
        float pz = __ldg(&vis[row*3+2]);
        float pt = (float)__ldg(&txt[row]);

        float Mv[4][4], Mt[4][4], Mb[4][4];
        #pragma unroll
        for (int q = 0; q < 4; ++q){
            float a0 = fmaf(px, sWv[q*12+0], fmaf(py, sWv[q*12+1],  fmaf(pz, sWv[q*12+2],  sbv[q*4+0])));
            float a1 = fmaf(px, sWv[q*12+3], fmaf(py, sWv[q*12+4],  fmaf(pz, sWv[q*12+5],  sbv[q*4+1])));
            float a2 = fmaf(px, sWv[q*12+6], fmaf(py, sWv[q*12+7],  fmaf(pz, sWv[q*12+8],  sbv[q*4+2])));
            float a3 = fmaf(px, sWv[q*12+9], fmaf(py, sWv[q*12+10], fmaf(pz, sWv[q*12+11], sbv[q*4+3])));
            float inv = inv_norm(fmaf(a0,a0, fmaf(a1,a1, fmaf(a2,a2, a3*a3))));
            Mv[q][0]=a0*inv; Mv[q][1]=a1*inv; Mv[q][2]=a2*inv; Mv[q][3]=a3*inv;

            float u0 = fmaf(pt, sWt[q*4+0], sbt[q*4+0]);
            float u1 = fmaf(pt, sWt[q*4+1], sbt[q*4+1]);
            float u2 = fmaf(pt, sWt[q*4+2], sbt[q*4+2]);
            float u3 = fmaf(pt, sWt[q*4+3], sbt[q*4+3]);
            inv = inv_norm(fmaf(u0,u0, fmaf(u1,u1, fmaf(u2,u2, u3*u3))));
            Mt[q][0]=u0*inv; Mt[q][1]=u1*inv; Mt[q][2]=u2*inv; Mt[q][3]=u3*inv;

            float w0 = Mv[q][0]+Mt[q][0], w1 = Mv[q][1]+Mt[q][1];
            float w2 = Mv[q][2]+Mt[q][2], w3 = Mv[q][3]+Mt[q][3];
            inv = inv_norm(fmaf(w0,w0, fmaf(w1,w1, fmaf(w2,w2, w3*w3))));
            Mb[q][0]=w0*inv; Mb[q][1]=w1*inv; Mb[q][2]=w2*inv; Mb[q][3]=w3*inv;
        }
        float ev = eta4(Mv), et = eta4(Mt), eb = eta4(Mb);
        out[OFF_ETA + 0*B_N + row] = ev;
        out[OFF_ETA + 1*B_N + row] = et;
        out[OFF_ETA + 2*B_N + row] = eb;

        unsigned m0 = __ballot_sync(0xffffffffu, ev != eb);
        unsigned m1 = __ballot_sync(0xffffffffu, et != eb);
        unsigned m2 = __ballot_sync(0xffffffffu, ev != et);
        if (lane == 0){ c0 += __popc(m0); c1 += __popc(m1); c2 += __popc(m2); }
    }
    if (lane == 0){
        if (c0) atomicAdd(&g_cnt[0], c0);
        if (c1) atomicAdd(&g_cnt[1], c1);
        if (c2) atomicAdd(&g_cnt[2], c2);
    }

    // ---- last-block-done: finalize scalars in-kernel ----
    __syncthreads();
    if (tid == 0){
        __threadfence();
        int prev = atomicAdd(&g_done, 1);
        if (prev == NBLK - 1){
            int n0 = atomicAdd(&g_cnt[0], 0);
            int n1 = atomicAdd(&g_cnt[1], 0);
            int n2 = atomicAdd(&g_cnt[2], 0);
            out[OFF_SCAL + 0] = sqrtf((float)n0) + sqrtf((float)n1);
            out[OFF_SCAL + 1] = (float)n2 * (1.0f / 262144.0f);
            g_cnt[0] = 0; g_cnt[1] = 0; g_cnt[2] = 0;   // reset for next graph replay
            g_done = 0;
        }
    }
}

extern "C" void kernel_launch(void* const* d_in, const int* in_sizes, int n_in,
                              void* d_out, int out_size)
{
    const float* vis = (const float*)d_in[0];
    const int*   txt = (const int*)  d_in[1];
    const float* Wv  = (const float*)d_in[2];
    const float* bv  = (const float*)d_in[3];
    const float* Wt  = (const float*)d_in[4];
    const float* bt  = (const float*)d_in[5];
    const float* Wd  = (const float*)d_in[6];
    const float* bd  = (const float*)d_in[7];
    float* out = (float*)d_out;

    bridge_kernel<<<NBLK, 256>>>(vis, txt, Wv, bv, Wt, bt, Wd, bd, out);
}